// round 9
// baseline (speedup 1.0000x reference)
#include <cuda_runtime.h>
#include <cuda_bf16.h>
#include <cstdint>
#include <math.h>

// ============================================================================
// DGCNN forward. K>=32 GEMMs use mma.sync bf16 (hi/lo split, fp32 acc):
//   A3 = [a_hi | a_lo | a_hi], B3 = [b_hi | b_hi | b_lo]  (K tripled)
//   => A3 . B3 = ah.bh + al.bh + ah.bl ~= fp32 exact (err ~2^-18)
// Dist GEMM exploits symmetry: lower-tri tiles only + mirrored smem-transpose
// writes. tc_gemm pinned to 2 CTAs/SM (launch_bounds) for latency hiding.
// Layer-1 kNN fully fused (K=3). A/Ct merged into one GEMM vs [Wa ; Wb-Wa].
// Top-k: warp-per-row in registers, 20 x warp-argmax, no block barriers.
// ============================================================================

#define BATCH   8
#define NPTS    2048
#define NROWS   (BATCH * NPTS)     // 16384
#define KNN     20
static __device__ __forceinline__ float lrelu(float x) { return x > 0.f ? x : 0.2f * x; }
#define BNS 0.9999950000374997f    // 1/sqrt(1+1e-5)

// ------------------------- scratch (device globals) -------------------------
__device__ float g_D [(long)BATCH * NPTS * NPTS];   // 134 MB inner products
__device__ float g_xx [NROWS];
__device__ int   g_idx[NROWS * KNN];
__device__ float g_ACt[(long)NROWS * 512];          // [A | Ct] merged, ld=2*O
__device__ float g_Wc [512 * 256];                  // concat weights fp32
__device__ float g_XC [NROWS * 512];                // concat(x1,x2,x3,x4)
__device__ float g_H  [NROWS * 1024];
__device__ float g_hpart[BATCH * 16 * 2048];
__device__ float g_feat [BATCH * 2048];
__device__ float g_fc1  [BATCH * 512];
__device__ float g_fc2  [BATCH * 256];
__device__ __align__(128) __nv_bfloat16 g_A3 [(long)NROWS * 1536];  // hi|lo|hi
__device__ __align__(128) __nv_bfloat16 g_B3 [(long)NROWS * 1536];  // hi|hi|lo
__device__ __align__(128) __nv_bfloat16 g_B3w[1024 * 1536];

// ------------------------- PTX helpers --------------------------------------
__device__ __forceinline__ uint32_t smem_u32(const void* p) {
    uint32_t a;
    asm("{ .reg .u64 t; cvta.to.shared.u64 t, %1; cvt.u32.u64 %0, t; }" : "=r"(a) : "l"(p));
    return a;
}
__device__ __forceinline__ void cp_async16(uint32_t s, const void* g, int src_bytes) {
    asm volatile("cp.async.cg.shared.global [%0], [%1], 16, %2;"
                 :: "r"(s), "l"(g), "r"(src_bytes));
}
__device__ __forceinline__ void ldm_x4(uint32_t a, uint32_t& r0, uint32_t& r1,
                                       uint32_t& r2, uint32_t& r3) {
    asm volatile("ldmatrix.sync.aligned.m8n8.x4.shared.b16 {%0,%1,%2,%3}, [%4];"
                 : "=r"(r0), "=r"(r1), "=r"(r2), "=r"(r3) : "r"(a));
}
__device__ __forceinline__ void mma_bf16(float* c, const uint32_t* a, const uint32_t* b) {
    asm volatile("mma.sync.aligned.m16n8k16.row.col.f32.bf16.bf16.f32 "
                 "{%0,%1,%2,%3}, {%4,%5,%6,%7}, {%8,%9}, {%0,%1,%2,%3};"
                 : "+f"(c[0]), "+f"(c[1]), "+f"(c[2]), "+f"(c[3])
                 : "r"(a[0]), "r"(a[1]), "r"(a[2]), "r"(a[3]), "r"(b[0]), "r"(b[1]));
}

// ------------------------- hi/lo split ---------------------------------------
__global__ void split_kernel(const float* __restrict__ X, int lda, int K, long MK,
                             __nv_bfloat16* __restrict__ A3, __nv_bfloat16* __restrict__ B3)
{
    long t = (long)blockIdx.x * blockDim.x + threadIdx.x;
    if (t >= MK) return;
    int m = (int)(t / K), k = (int)(t % K);
    float v = X[(long)m * lda + k];
    __nv_bfloat16 hi = __float2bfloat16(v);
    __nv_bfloat16 lo = __float2bfloat16(v - __bfloat162float(hi));
    long base = (long)m * (3 * K);
    if (A3) { A3[base + k] = hi; A3[base + K + k] = lo; A3[base + 2 * K + k] = hi; }
    if (B3) { B3[base + k] = hi; B3[base + K + k] = hi; B3[base + 2 * K + k] = lo; }
}

// ------------------------- mma.sync GEMM  C = A3 @ B3^T ---------------------
// CTA tile 128x128, K-chunk 32, double-buffered cp.async, 8 warps of 64x32.
// 2 CTAs/SM pinned via launch_bounds for cross-CTA latency hiding.
// SYM=true: lower-tri tiles only; bx<by also writes the mirrored tile.
#define TPAD 40   // bf16 elems per smem row (32 data + 8 pad) -> 80B stride

template<bool SYM>
__global__ __launch_bounds__(256, 2)
void tc_gemm_kernel(const __nv_bfloat16* __restrict__ A, int lda, long sA,
                    const __nv_bfloat16* __restrict__ B, int ldb, long sB,
                    float* __restrict__ C, int ldc, long sC,
                    int K3, int Ntot,
                    const float* __restrict__ gvec, const float* __restrict__ bvec)
{
    if (SYM && blockIdx.x > blockIdx.y) return;

    __shared__ __align__(16) __nv_bfloat16 sbuf[2][2][128 * TPAD];  // 40 KB

    int tid = threadIdx.x, wid = tid >> 5, lane = tid & 31;
    A += (long)blockIdx.z * sA; B += (long)blockIdx.z * sB; C += (long)blockIdx.z * sC;
    long rowBase = (long)blockIdx.y * 128;
    long colBase = (long)blockIdx.x * 128;

    int warp_m = wid & 1;
    int warp_n = wid >> 1;

    uint32_t sa_base[2] = { smem_u32(sbuf[0][0]), smem_u32(sbuf[0][1]) };
    uint32_t sb_base[2] = { smem_u32(sbuf[1][0]), smem_u32(sbuf[1][1]) };

    int ldr0 = (tid * 2) >> 2,     lds0 = (tid * 2) & 3;
    int ldr1 = (tid * 2 + 1) >> 2, lds1 = (tid * 2 + 1) & 3;

    int nch = K3 >> 5;
    float acc[4][4][4] = {};

    {
        const __nv_bfloat16* Ag = A + rowBase * lda;
        const __nv_bfloat16* Bg = B + colBase * ldb;
        cp_async16(sa_base[0] + (ldr0 * TPAD + lds0 * 8) * 2, Ag + (long)ldr0 * lda + lds0 * 8, 16);
        cp_async16(sa_base[0] + (ldr1 * TPAD + lds1 * 8) * 2, Ag + (long)ldr1 * lda + lds1 * 8, 16);
        int v0 = (colBase + ldr0 < Ntot) ? 16 : 0;
        int v1 = (colBase + ldr1 < Ntot) ? 16 : 0;
        cp_async16(sb_base[0] + (ldr0 * TPAD + lds0 * 8) * 2, Bg + (long)ldr0 * ldb + lds0 * 8, v0);
        cp_async16(sb_base[0] + (ldr1 * TPAD + lds1 * 8) * 2, Bg + (long)ldr1 * ldb + lds1 * 8, v1);
        asm volatile("cp.async.commit_group;");
    }

    int buf = 0;
    for (int ch = 0; ch < nch; ch++) {
        if (ch + 1 < nch) {
            const __nv_bfloat16* Ag = A + rowBase * lda + (ch + 1) * 32;
            const __nv_bfloat16* Bg = B + colBase * ldb + (ch + 1) * 32;
            int nb = buf ^ 1;
            cp_async16(sa_base[nb] + (ldr0 * TPAD + lds0 * 8) * 2, Ag + (long)ldr0 * lda + lds0 * 8, 16);
            cp_async16(sa_base[nb] + (ldr1 * TPAD + lds1 * 8) * 2, Ag + (long)ldr1 * lda + lds1 * 8, 16);
            int v0 = (colBase + ldr0 < Ntot) ? 16 : 0;
            int v1 = (colBase + ldr1 < Ntot) ? 16 : 0;
            cp_async16(sb_base[nb] + (ldr0 * TPAD + lds0 * 8) * 2, Bg + (long)ldr0 * ldb + lds0 * 8, v0);
            cp_async16(sb_base[nb] + (ldr1 * TPAD + lds1 * 8) * 2, Bg + (long)ldr1 * ldb + lds1 * 8, v1);
            asm volatile("cp.async.commit_group;");
            asm volatile("cp.async.wait_group 1;");
        } else {
            asm volatile("cp.async.wait_group 0;");
        }
        __syncthreads();

#pragma unroll
        for (int ks = 0; ks < 2; ks++) {
            uint32_t afr[4][4], bfr[4][2];
#pragma unroll
            for (int mt = 0; mt < 4; mt++) {
                int r = warp_m * 64 + mt * 16 + (lane & 15);
                int c = ks * 16 + (lane >> 4) * 8;
                ldm_x4(sa_base[buf] + (r * TPAD + c) * 2,
                       afr[mt][0], afr[mt][1], afr[mt][2], afr[mt][3]);
            }
#pragma unroll
            for (int np = 0; np < 2; np++) {
                int r = warp_n * 32 + np * 16 + (lane & 7) + ((lane & 16) >> 1);
                int c = ks * 16 + ((lane >> 3) & 1) * 8;
                uint32_t r0, r1, r2, r3;
                ldm_x4(sb_base[buf] + (r * TPAD + c) * 2, r0, r1, r2, r3);
                bfr[np * 2][0] = r0; bfr[np * 2][1] = r1;
                bfr[np * 2 + 1][0] = r2; bfr[np * 2 + 1][1] = r3;
            }
#pragma unroll
            for (int mt = 0; mt < 4; mt++)
#pragma unroll
                for (int nt = 0; nt < 4; nt++)
                    mma_bf16(acc[mt][nt], afr[mt], bfr[nt]);
        }
        __syncthreads();
        buf ^= 1;
    }

    // ---- normal epilogue ----
#pragma unroll
    for (int mt = 0; mt < 4; mt++) {
#pragma unroll
        for (int nt = 0; nt < 4; nt++) {
            int n0 = (int)colBase + warp_n * 32 + nt * 8 + (lane & 3) * 2;
            if (n0 >= Ntot) continue;
            long m0 = rowBase + warp_m * 64 + mt * 16 + (lane >> 2);
            float v0 = acc[mt][nt][0], v1 = acc[mt][nt][1];
            float v2 = acc[mt][nt][2], v3 = acc[mt][nt][3];
            if (gvec) {
                float ga = gvec[n0], gb = gvec[n0 + 1], ba = bvec[n0], bb = bvec[n0 + 1];
                v0 = lrelu(ga * (v0 * BNS) + ba); v1 = lrelu(gb * (v1 * BNS) + bb);
                v2 = lrelu(ga * (v2 * BNS) + ba); v3 = lrelu(gb * (v3 * BNS) + bb);
            }
            *(float2*)(C + m0 * ldc + n0)       = make_float2(v0, v1);
            *(float2*)(C + (m0 + 8) * ldc + n0) = make_float2(v2, v3);
        }
    }

    // ---- mirror epilogue (SYM, off-diagonal): write transposed tile ----
    if (SYM && blockIdx.x < blockIdx.y) {
        float* stage = (float*)sbuf;        // 40 KB available, need 64*133*4 B
        const int SST = 133;
#pragma unroll
        for (int p = 0; p < 2; p++) {
            __syncthreads();
            if (warp_m == p) {
#pragma unroll
                for (int mt = 0; mt < 4; mt++)
#pragma unroll
                    for (int nt = 0; nt < 4; nt++)
#pragma unroll
                        for (int v = 0; v < 4; v++) {
                            int r = mt * 16 + (lane >> 2) + ((v & 2) ? 8 : 0);
                            int c = warp_n * 32 + nt * 8 + (lane & 3) * 2 + (v & 1);
                            stage[r * SST + c] = acc[mt][nt][v];
                        }
            }
            __syncthreads();
#pragma unroll
            for (int n = wid * 16; n < wid * 16 + 16; n++) {
                float a = stage[(2 * lane) * SST + n];
                float b = stage[(2 * lane + 1) * SST + n];
                *(float2*)(C + (colBase + n) * (long)ldc + rowBase + p * 64 + 2 * lane)
                    = make_float2(a, b);
            }
        }
    }
}

// ------------------------- SIMT GEMM (layer-1 A/Ct, K=3) --------------------
__global__ __launch_bounds__(256)
void gemm_tn_kernel(const float* __restrict__ A, int lda,
                    const float* __restrict__ B, int ldb,
                    float* __restrict__ C, int ldc,
                    int M, int N, int K)
{
    __shared__ float As[64][17];
    __shared__ float Bs[64][17];
    int tx = threadIdx.x, ty = threadIdx.y;
    int tid = ty * 16 + tx;
    int rowBase = blockIdx.y * 64;
    int colBase = blockIdx.x * 64;
    float acc[4][4] = {};
    for (int kk = 0; kk < K; kk += 16) {
#pragma unroll
        for (int l = 0; l < 4; l++) {
            int e = tid + l * 256;
            int r = e >> 4, k = e & 15;
            As[r][k] = (kk + k < K) ? A[(long)(rowBase + r) * lda + kk + k] : 0.f;
            Bs[r][k] = (kk + k < K && colBase + r < N) ? B[(long)(colBase + r) * ldb + kk + k] : 0.f;
        }
        __syncthreads();
#pragma unroll
        for (int k = 0; k < 16; k++) {
            float a[4], b[4];
#pragma unroll
            for (int i = 0; i < 4; i++) a[i] = As[ty * 4 + i][k];
#pragma unroll
            for (int j = 0; j < 4; j++) b[j] = Bs[tx * 4 + j][k];
#pragma unroll
            for (int i = 0; i < 4; i++)
#pragma unroll
                for (int j = 0; j < 4; j++) acc[i][j] = fmaf(a[i], b[j], acc[i][j]);
        }
        __syncthreads();
    }
#pragma unroll
    for (int i = 0; i < 4; i++) {
        int rrow = rowBase + ty * 4 + i;
        if (rrow >= M) continue;
#pragma unroll
        for (int j = 0; j < 4; j++) {
            int col = colBase + tx * 4 + j;
            if (col >= N) continue;
            C[(long)rrow * ldc + col] = acc[i][j];
        }
    }
}

// ------------------------- per-point squared norm ----------------------------
__global__ void xx_kernel(const float* __restrict__ X, int lda, int C, float* __restrict__ xx)
{
    int r = blockIdx.x * blockDim.x + threadIdx.x;
    if (r >= NROWS) return;
    float s = 0.f;
    for (int c = 0; c < C; c++) { float v = X[(long)r * lda + c]; s += v * v; }
    xx[r] = s;
}

// ------------------------- layer-1 fused kNN (K=3, no D) --------------------
#define TPK_SEG 64     // 2048 / 32 lanes
__global__ __launch_bounds__(256)
void knn3_fused_kernel(const float* __restrict__ X, int* __restrict__ idxout)
{
    __shared__ float sX[NPTS], sY[NPTS], sZ[NPTS], sN[NPTS];
    int tid = threadIdx.x, wid = tid >> 5, lane = tid & 31;
    int b = blockIdx.y;
    const float* Xb = X + (long)b * NPTS * 3;

    for (int j = tid; j < NPTS; j += 256) {
        float x = Xb[j * 3], y = Xb[j * 3 + 1], z = Xb[j * 3 + 2];
        sX[j] = x; sY[j] = y; sZ[j] = z;
        float s = 0.f; s = fmaf(x, x, s); s = fmaf(y, y, s); s = fmaf(z, z, s);
        sN[j] = s;
    }
    __syncthreads();

    int i = blockIdx.x * 8 + wid;
    float xi = sX[i], yi = sY[i], zi = sZ[i], ni = sN[i];

    float vals[TPK_SEG];
#pragma unroll
    for (int t = 0; t < TPK_SEG; t++) {
        int j = lane + (t << 5);
        float d = 0.f;
        d = fmaf(xi, sX[j], d); d = fmaf(yi, sY[j], d); d = fmaf(zi, sZ[j], d);
        vals[t] = 2.f * d - ni - sN[j];
    }

    float lmax = vals[0]; int lt = 0;
#pragma unroll
    for (int t = 1; t < TPK_SEG; t++)
        if (vals[t] > lmax) { lmax = vals[t]; lt = t; }

    int* orow = idxout + ((long)b * NPTS + i) * KNN;
    for (int r = 0; r < KNN; r++) {
        float v = lmax;
        int   j = lane + (lt << 5);
#pragma unroll
        for (int d = 16; d; d >>= 1) {
            float ov = __shfl_xor_sync(0xffffffffu, v, d);
            int   oj = __shfl_xor_sync(0xffffffffu, j, d);
            if (ov > v || (ov == v && oj < j)) { v = ov; j = oj; }
        }
        if (lane == 0) orow[r] = j;
        if ((j & 31) == lane) {
            vals[j >> 5] = -1e30f;
            lmax = vals[0]; lt = 0;
#pragma unroll
            for (int t = 1; t < TPK_SEG; t++)
                if (vals[t] > lmax) { lmax = vals[t]; lt = t; }
        }
    }
}

// ------------------------- top-20 per row (layers 2-4) -----------------------
__global__ __launch_bounds__(256)
void topk_warp_kernel(const float* __restrict__ D, const float* __restrict__ xx,
                      int* __restrict__ idxout)
{
    int wid = threadIdx.x >> 5, lane = threadIdx.x & 31;
    int row = blockIdx.x * 8 + wid;
    int b = row >> 11, i = row & 2047;

    const float* Drow = D + (long)b * NPTS * NPTS + (long)i * NPTS;
    const float* xxb  = xx + b * NPTS;
    float xi = xxb[i];

    float vals[TPK_SEG];
#pragma unroll
    for (int t = 0; t < TPK_SEG; t++) {
        int j = lane + (t << 5);
        vals[t] = 2.f * Drow[j] - xi - xxb[j];
    }

    float lmax = vals[0]; int lt = 0;
#pragma unroll
    for (int t = 1; t < TPK_SEG; t++)
        if (vals[t] > lmax) { lmax = vals[t]; lt = t; }

    int* orow = idxout + row * KNN;
    for (int r = 0; r < KNN; r++) {
        float v = lmax;
        int   j = lane + (lt << 5);
#pragma unroll
        for (int d = 16; d; d >>= 1) {
            float ov = __shfl_xor_sync(0xffffffffu, v, d);
            int   oj = __shfl_xor_sync(0xffffffffu, j, d);
            if (ov > v || (ov == v && oj < j)) { v = ov; j = oj; }
        }
        if (lane == 0) orow[r] = j;
        if ((j & 31) == lane) {
            vals[j >> 5] = -1e30f;
            lmax = vals[0]; lt = 0;
#pragma unroll
            for (int t = 1; t < TPK_SEG; t++)
                if (vals[t] > lmax) { lmax = vals[t]; lt = t; }
        }
    }
}

// ------------------------- concat weights [Wa ; Wb-Wa] -----------------------
__global__ void wcat_kernel(const float* __restrict__ W, int C, int O, float* __restrict__ Wc)
{
    int t = blockIdx.x * blockDim.x + threadIdx.x;
    if (t >= O * C) return;
    int o = t / C, c = t % C;
    float wa = W[o * 2 * C + c], wb = W[o * 2 * C + C + c];
    Wc[o * C + c] = wa;
    Wc[(O + o) * C + c] = wb - wa;
}

// ------------------------- neighbor aggregate (merged A|Ct) ------------------
__global__ void agg_kernel(const float* __restrict__ ACt,
                           const int* __restrict__ idx,
                           const float* __restrict__ gv, const float* __restrict__ bv,
                           int O, float* __restrict__ out, int ldout)
{
    int row = blockIdx.x;
    int b = row >> 11;
    int o = threadIdx.x;
    int ld = 2 * O;
    __shared__ int sidx[KNN];
    if (o < KNN) sidx[o] = idx[row * KNN + o];
    __syncthreads();
    float c  = ACt[(long)row * ld + O + o];
    float gg = gv[o], bb = bv[o];
    float m = -1e30f;
#pragma unroll
    for (int j = 0; j < KNN; j++) {
        float v = ACt[((long)(b << 11) + sidx[j]) * ld + o] + c;
        v = lrelu(gg * (v * BNS) + bb);
        m = fmaxf(m, v);
    }
    out[(long)row * ldout + o] = m;
}

// ------------------------- global pool ---------------------------------------
__global__ void hpart_kernel(const float* __restrict__ H, float* __restrict__ part)
{
    int b = blockIdx.x >> 4, c = blockIdx.x & 15;
    int o = threadIdx.x;
    float mx = -1e30f, sm = 0.f;
    int n0 = c * 128;
    for (int n = n0; n < n0 + 128; n++) {
        float v = H[((long)(b * NPTS + n)) * 1024 + o];
        mx = fmaxf(mx, v); sm += v;
    }
    part[(long)blockIdx.x * 2048 + o]        = mx;
    part[(long)blockIdx.x * 2048 + 1024 + o] = sm;
}
__global__ void hcombine_kernel(const float* __restrict__ part, float* __restrict__ feat)
{
    int b = blockIdx.x, o = threadIdx.x;
    float mx = -1e30f, sm = 0.f;
    for (int c = 0; c < 16; c++) {
        mx = fmaxf(mx, part[(long)(b * 16 + c) * 2048 + o]);
        sm += part[(long)(b * 16 + c) * 2048 + 1024 + o];
    }
    feat[b * 2048 + o]        = mx;
    feat[b * 2048 + 1024 + o] = sm * (1.f / 2048.f);
}

// ------------------------- small FC -------------------------------------------
__global__ void fc_kernel(const float* __restrict__ in, int K,
                          const float* __restrict__ W, const float* __restrict__ bias,
                          const float* __restrict__ gv, const float* __restrict__ bv,
                          float* __restrict__ out, int O, int doLrelu)
{
    int gw = (blockIdx.x * blockDim.x + threadIdx.x) >> 5;
    int lane = threadIdx.x & 31;
    if (gw >= BATCH * O) return;
    int b = gw / O, o = gw % O;
    float s = 0.f;
    for (int k = lane; k < K; k += 32) s += in[b * K + k] * W[o * K + k];
#pragma unroll
    for (int d = 16; d; d >>= 1) s += __shfl_down_sync(0xffffffffu, s, d);
    if (lane == 0) {
        if (bias) s += bias[o];
        if (gv)   s = gv[o] * (s * BNS) + bv[o];
        if (doLrelu) s = lrelu(s);
        out[b * O + o] = s;
    }
}

// ============================================================================
static void edge_layer_tc(const float* Xin, int lda, int C,
                          const float* W, const float* gv, const float* bv, int O,
                          float* outcol, int ldout,
                          float* dD, float* dxx, int* didx, float* dWc, float* dACt,
                          __nv_bfloat16* dA3, __nv_bfloat16* dB3, __nv_bfloat16* dB3w)
{
    int K3 = 3 * C;
    xx_kernel<<<(NROWS + 255) / 256, 256>>>(Xin, lda, C, dxx);
    long MK = (long)NROWS * C;
    split_kernel<<<(unsigned)((MK + 255) / 256), 256>>>(Xin, lda, C, MK, dA3, dB3);
    // dist = X @ X^T, symmetric: lower-tri tiles only + mirrored writes
    tc_gemm_kernel<true><<<dim3(NPTS / 128, NPTS / 128, BATCH), 256>>>(
        dA3, K3, (long)NPTS * K3, dB3, K3, (long)NPTS * K3,
        dD, NPTS, (long)NPTS * NPTS, K3, NPTS, nullptr, nullptr);
    topk_warp_kernel<<<NROWS / 8, 256>>>(dD, dxx, didx);
    // [A | Ct] = X @ [Wa ; Wb-Wa]^T in ONE GEMM (N = 2*O)
    wcat_kernel<<<(O * C + 255) / 256, 256>>>(W, C, O, dWc);
    split_kernel<<<(2 * O * C + 255) / 256, 256>>>(dWc, C, C, (long)2 * O * C, nullptr, dB3w);
    tc_gemm_kernel<false><<<dim3((2 * O + 127) / 128, NROWS / 128, 1), 256>>>(
        dA3, K3, 0, dB3w, K3, 0, dACt, 2 * O, 0, K3, 2 * O, nullptr, nullptr);
    agg_kernel<<<NROWS, O>>>(dACt, didx, gv, bv, O, outcol, ldout);
}

extern "C" void kernel_launch(void* const* d_in, const int* in_sizes, int n_in,
                              void* d_out, int out_size)
{
    const float* x   = (const float*)d_in[0];
    const float* W1  = (const float*)d_in[1];
    const float* g1  = (const float*)d_in[2];
    const float* b1  = (const float*)d_in[3];
    const float* W2  = (const float*)d_in[4];
    const float* g2  = (const float*)d_in[5];
    const float* b2  = (const float*)d_in[6];
    const float* W3  = (const float*)d_in[7];
    const float* g3  = (const float*)d_in[8];
    const float* b3  = (const float*)d_in[9];
    const float* W4  = (const float*)d_in[10];
    const float* g4  = (const float*)d_in[11];
    const float* b4  = (const float*)d_in[12];
    const float* W5  = (const float*)d_in[13];
    const float* g5  = (const float*)d_in[14];
    const float* b5  = (const float*)d_in[15];
    const float* L1  = (const float*)d_in[16];
    const float* g6  = (const float*)d_in[17];
    const float* b6  = (const float*)d_in[18];
    const float* L2  = (const float*)d_in[19];
    const float* L2b = (const float*)d_in[20];
    const float* g7  = (const float*)d_in[21];
    const float* b7  = (const float*)d_in[22];
    const float* L3  = (const float*)d_in[23];
    const float* L3b = (const float*)d_in[24];
    float* out = (float*)d_out;

    float *dD, *dxx, *dACt, *dWc, *dXC, *dH, *dPart, *dFeat, *dFc1, *dFc2;
    int* didx;
    __nv_bfloat16 *dA3, *dB3, *dB3w;
    cudaGetSymbolAddress((void**)&dD,    g_D);
    cudaGetSymbolAddress((void**)&dxx,   g_xx);
    cudaGetSymbolAddress((void**)&didx,  g_idx);
    cudaGetSymbolAddress((void**)&dACt,  g_ACt);
    cudaGetSymbolAddress((void**)&dWc,   g_Wc);
    cudaGetSymbolAddress((void**)&dXC,   g_XC);
    cudaGetSymbolAddress((void**)&dH,    g_H);
    cudaGetSymbolAddress((void**)&dPart, g_hpart);
    cudaGetSymbolAddress((void**)&dFeat, g_feat);
    cudaGetSymbolAddress((void**)&dFc1,  g_fc1);
    cudaGetSymbolAddress((void**)&dFc2,  g_fc2);
    cudaGetSymbolAddress((void**)&dA3,   g_A3);
    cudaGetSymbolAddress((void**)&dB3,   g_B3);
    cudaGetSymbolAddress((void**)&dB3w,  g_B3w);

    // ---- layer 1 (K=3): fused kNN + tiny SIMT GEMM ----
    {
        knn3_fused_kernel<<<dim3(NPTS / 8, BATCH), 256>>>(x, didx);
        wcat_kernel<<<(64 * 3 + 255) / 256, 256>>>(W1, 3, 64, dWc);
        gemm_tn_kernel<<<dim3(2, NROWS / 64), dim3(16, 16)>>>(
            x, 3, dWc, 3, dACt, 128, NROWS, 128, 3);
        agg_kernel<<<NROWS, 64>>>(dACt, didx, g1, b1, 64, dXC + 0, 512);
    }

    // ---- layers 2-4: mma.sync path ----
    edge_layer_tc(dXC + 0,   512, 64,  W2, g2, b2,  64, dXC + 64,  512,
                  dD, dxx, didx, dWc, dACt, dA3, dB3, dB3w);
    edge_layer_tc(dXC + 64,  512, 64,  W3, g3, b3, 128, dXC + 128, 512,
                  dD, dxx, didx, dWc, dACt, dA3, dB3, dB3w);
    edge_layer_tc(dXC + 128, 512, 128, W4, g4, b4, 256, dXC + 256, 512,
                  dD, dxx, didx, dWc, dACt, dA3, dB3, dB3w);

    // ---- h = lrelu(bn(XC @ W5^T)) on tensor cores ----
    {
        long MK = (long)NROWS * 512;
        split_kernel<<<(unsigned)((MK + 255) / 256), 256>>>(dXC, 512, 512, MK, dA3, nullptr);
        split_kernel<<<(1024 * 512 + 255) / 256, 256>>>(W5, 512, 512, (long)1024 * 512, nullptr, dB3w);
        tc_gemm_kernel<false><<<dim3(1024 / 128, NROWS / 128, 1), 256>>>(
            dA3, 1536, 0, dB3w, 1536, 0, dH, 1024, 0, 1536, 1024, g5, b5);
    }

    // ---- global pool + FC head ----
    hpart_kernel<<<BATCH * 16, 1024>>>(dH, dPart);
    hcombine_kernel<<<BATCH, 1024>>>(dPart, dFeat);
    fc_kernel<<<(BATCH * 512 * 32 + 255) / 256, 256>>>(dFeat, 2048, L1, nullptr, g6, b6, dFc1, 512, 1);
    fc_kernel<<<(BATCH * 256 * 32 + 255) / 256, 256>>>(dFc1,  512,  L2, L2b,    g7, b7, dFc2, 256, 1);
    fc_kernel<<<(BATCH * 10  * 32 + 255) / 256, 256>>>(dFc2,  256,  L3, L3b,    nullptr, nullptr, out, 10, 0);
}

// round 10
// speedup vs baseline: 1.0333x; 1.0333x over previous
#include <cuda_runtime.h>
#include <cuda_bf16.h>
#include <cstdint>
#include <math.h>

// ============================================================================
// DGCNN forward. K>=32 GEMMs use mma.sync bf16 (hi/lo split, fp32 acc):
//   A3 = [a_hi | a_lo | a_hi], B3 = [b_hi | b_hi | b_lo]  (K tripled)
//   => A3 . B3 = ah.bh + al.bh + ah.bl ~= fp32 exact (err ~2^-18)
// tc_gemm: 4-stage cp.async circular pipeline (80 KB dynamic smem).
// Dist GEMM exploits symmetry (lower-tri tiles + mirrored smem-transpose).
// Fused prologues: splitxx (A3+B3+xx in one pass), wcatsplit (weights->bf16).
// Layer-1 kNN fully fused (K=3). A/Ct merged into one GEMM vs [Wa ; Wb-Wa].
// Top-k: warp-per-row in registers, 20 x warp-argmax, no block barriers.
// ============================================================================

#define BATCH   8
#define NPTS    2048
#define NROWS   (BATCH * NPTS)     // 16384
#define KNN     20
static __device__ __forceinline__ float lrelu(float x) { return x > 0.f ? x : 0.2f * x; }
#define BNS 0.9999950000374997f    // 1/sqrt(1+1e-5)

// ------------------------- scratch (device globals) -------------------------
__device__ float g_D [(long)BATCH * NPTS * NPTS];   // 134 MB inner products
__device__ float g_xx [NROWS];
__device__ int   g_idx[NROWS * KNN];
__device__ float g_ACt[(long)NROWS * 512];          // [A | Ct] merged, ld=2*O
__device__ float g_Wc [512 * 256];                  // concat weights fp32 (layer1)
__device__ float g_XC [NROWS * 512];                // concat(x1,x2,x3,x4)
__device__ float g_H  [NROWS * 1024];
__device__ float g_hpart[BATCH * 16 * 2048];
__device__ float g_feat [BATCH * 2048];
__device__ float g_fc1  [BATCH * 512];
__device__ float g_fc2  [BATCH * 256];
__device__ __align__(128) __nv_bfloat16 g_A3 [(long)NROWS * 1536];  // hi|lo|hi
__device__ __align__(128) __nv_bfloat16 g_B3 [(long)NROWS * 1536];  // hi|hi|lo
__device__ __align__(128) __nv_bfloat16 g_B3w[1024 * 1536];

// ------------------------- PTX helpers --------------------------------------
__device__ __forceinline__ uint32_t smem_u32(const void* p) {
    uint32_t a;
    asm("{ .reg .u64 t; cvta.to.shared.u64 t, %1; cvt.u32.u64 %0, t; }" : "=r"(a) : "l"(p));
    return a;
}
__device__ __forceinline__ void cp_async16(uint32_t s, const void* g, int src_bytes) {
    asm volatile("cp.async.cg.shared.global [%0], [%1], 16, %2;"
                 :: "r"(s), "l"(g), "r"(src_bytes));
}
__device__ __forceinline__ void ldm_x4(uint32_t a, uint32_t& r0, uint32_t& r1,
                                       uint32_t& r2, uint32_t& r3) {
    asm volatile("ldmatrix.sync.aligned.m8n8.x4.shared.b16 {%0,%1,%2,%3}, [%4];"
                 : "=r"(r0), "=r"(r1), "=r"(r2), "=r"(r3) : "r"(a));
}
__device__ __forceinline__ void mma_bf16(float* c, const uint32_t* a, const uint32_t* b) {
    asm volatile("mma.sync.aligned.m16n8k16.row.col.f32.bf16.bf16.f32 "
                 "{%0,%1,%2,%3}, {%4,%5,%6,%7}, {%8,%9}, {%0,%1,%2,%3};"
                 : "+f"(c[0]), "+f"(c[1]), "+f"(c[2]), "+f"(c[3])
                 : "r"(a[0]), "r"(a[1]), "r"(a[2]), "r"(a[3]), "r"(b[0]), "r"(b[1]));
}

// ------------------------- fused split (+optional xx), warp per row ---------
__global__ void splitxx_kernel(const float* __restrict__ X, int lda, int K, int M,
                               __nv_bfloat16* __restrict__ A3,
                               __nv_bfloat16* __restrict__ B3,
                               float* __restrict__ xx)
{
    int w = (blockIdx.x * blockDim.x + threadIdx.x) >> 5;
    int lane = threadIdx.x & 31;
    if (w >= M) return;
    const float* row = X + (long)w * lda;
    long base = (long)w * (3 * K);
    float s = 0.f;
    for (int k = lane; k < K; k += 32) {
        float v = row[k];
        __nv_bfloat16 hi = __float2bfloat16(v);
        __nv_bfloat16 lo = __float2bfloat16(v - __bfloat162float(hi));
        if (A3) { A3[base + k] = hi; A3[base + K + k] = lo; A3[base + 2 * K + k] = hi; }
        if (B3) { B3[base + k] = hi; B3[base + K + k] = hi; B3[base + 2 * K + k] = lo; }
        s = fmaf(v, v, s);
    }
    if (xx) {
#pragma unroll
        for (int d = 16; d; d >>= 1) s += __shfl_xor_sync(0xffffffffu, s, d);
        if (lane == 0) xx[w] = s;
    }
}

// ------------------------- fused wcat + split (weights -> B3 triple) --------
__global__ void wcatsplit_kernel(const float* __restrict__ W, int C, int O,
                                 __nv_bfloat16* __restrict__ B3w)
{
    int t = blockIdx.x * blockDim.x + threadIdx.x;
    if (t >= 2 * O * C) return;
    int o = t / C, c = t % C;
    float v = (o < O) ? W[o * 2 * C + c]
                      : (W[(o - O) * 2 * C + C + c] - W[(o - O) * 2 * C + c]);
    __nv_bfloat16 hi = __float2bfloat16(v);
    __nv_bfloat16 lo = __float2bfloat16(v - __bfloat162float(hi));
    long base = (long)o * (3 * C);
    B3w[base + c] = hi; B3w[base + C + c] = hi; B3w[base + 2 * C + c] = lo;
}

// ------------------------- mma.sync GEMM  C = A3 @ B3^T ---------------------
// CTA tile 128x128, K-chunk 32, 4-stage cp.async circular pipeline.
// SYM=true: lower-tri tiles only; bx<by also writes the mirrored tile.
#define TPAD 40                 // bf16/row (32 data + 8 pad) -> 80 B stride
#define STAGE_B (2 * 128 * TPAD * 2)   // bytes per stage (A buf + B buf) = 20480
#define SMEM_TC (4 * STAGE_B)          // 81920

template<bool SYM>
__global__ __launch_bounds__(256)
void tc_gemm_kernel(const __nv_bfloat16* __restrict__ A, int lda, long sA,
                    const __nv_bfloat16* __restrict__ B, int ldb, long sB,
                    float* __restrict__ C, int ldc, long sC,
                    int K3, int Ntot,
                    const float* __restrict__ gvec, const float* __restrict__ bvec)
{
    if (SYM && blockIdx.x > blockIdx.y) return;

    extern __shared__ __align__(16) char sbuf[];

    int tid = threadIdx.x, wid = tid >> 5, lane = tid & 31;
    A += (long)blockIdx.z * sA; B += (long)blockIdx.z * sB; C += (long)blockIdx.z * sC;
    long rowBase = (long)blockIdx.y * 128;
    long colBase = (long)blockIdx.x * 128;

    int warp_m = wid & 1;
    int warp_n = wid >> 1;

    uint32_t smem0 = smem_u32(sbuf);
    int ldr0 = (tid * 2) >> 2,     lds0 = (tid * 2) & 3;
    int ldr1 = (tid * 2 + 1) >> 2, lds1 = (tid * 2 + 1) & 3;

    int nch = K3 >> 5;
    float acc[4][4][4] = {};

    int vb0 = (colBase + ldr0 < Ntot) ? 16 : 0;
    int vb1 = (colBase + ldr1 < Ntot) ? 16 : 0;

    // preload chunks 0..2
#pragma unroll
    for (int p = 0; p < 3; p++) {
        if (p < nch) {
            uint32_t sa = smem0 + p * STAGE_B;
            uint32_t sb = sa + 128 * TPAD * 2;
            const __nv_bfloat16* Ag = A + rowBase * lda + p * 32;
            const __nv_bfloat16* Bg = B + colBase * ldb + p * 32;
            cp_async16(sa + (ldr0 * TPAD + lds0 * 8) * 2, Ag + (long)ldr0 * lda + lds0 * 8, 16);
            cp_async16(sa + (ldr1 * TPAD + lds1 * 8) * 2, Ag + (long)ldr1 * lda + lds1 * 8, 16);
            cp_async16(sb + (ldr0 * TPAD + lds0 * 8) * 2, Bg + (long)ldr0 * ldb + lds0 * 8, vb0);
            cp_async16(sb + (ldr1 * TPAD + lds1 * 8) * 2, Bg + (long)ldr1 * ldb + lds1 * 8, vb1);
        }
        asm volatile("cp.async.commit_group;");
    }

    for (int ch = 0; ch < nch; ch++) {
        int nxt = ch + 3;
        if (nxt < nch) {
            int st = nxt & 3;
            uint32_t sa = smem0 + st * STAGE_B;
            uint32_t sb = sa + 128 * TPAD * 2;
            const __nv_bfloat16* Ag = A + rowBase * lda + nxt * 32;
            const __nv_bfloat16* Bg = B + colBase * ldb + nxt * 32;
            cp_async16(sa + (ldr0 * TPAD + lds0 * 8) * 2, Ag + (long)ldr0 * lda + lds0 * 8, 16);
            cp_async16(sa + (ldr1 * TPAD + lds1 * 8) * 2, Ag + (long)ldr1 * lda + lds1 * 8, 16);
            cp_async16(sb + (ldr0 * TPAD + lds0 * 8) * 2, Bg + (long)ldr0 * ldb + lds0 * 8, vb0);
            cp_async16(sb + (ldr1 * TPAD + lds1 * 8) * 2, Bg + (long)ldr1 * ldb + lds1 * 8, vb1);
            asm volatile("cp.async.commit_group;");
        }
        int rem = nch - 1 - ch;
        if (nxt < nch)      asm volatile("cp.async.wait_group 3;");
        else if (rem == 2)  asm volatile("cp.async.wait_group 2;");
        else if (rem == 1)  asm volatile("cp.async.wait_group 1;");
        else                asm volatile("cp.async.wait_group 0;");
        __syncthreads();

        int st = ch & 3;
        uint32_t sa_b = smem0 + st * STAGE_B;
        uint32_t sb_b = sa_b + 128 * TPAD * 2;

#pragma unroll
        for (int ks = 0; ks < 2; ks++) {
            uint32_t afr[4][4], bfr[4][2];
#pragma unroll
            for (int mt = 0; mt < 4; mt++) {
                int r = warp_m * 64 + mt * 16 + (lane & 15);
                int c = ks * 16 + (lane >> 4) * 8;
                ldm_x4(sa_b + (r * TPAD + c) * 2,
                       afr[mt][0], afr[mt][1], afr[mt][2], afr[mt][3]);
            }
#pragma unroll
            for (int np = 0; np < 2; np++) {
                int r = warp_n * 32 + np * 16 + (lane & 7) + ((lane & 16) >> 1);
                int c = ks * 16 + ((lane >> 3) & 1) * 8;
                uint32_t r0, r1, r2, r3;
                ldm_x4(sb_b + (r * TPAD + c) * 2, r0, r1, r2, r3);
                bfr[np * 2][0] = r0; bfr[np * 2][1] = r1;
                bfr[np * 2 + 1][0] = r2; bfr[np * 2 + 1][1] = r3;
            }
#pragma unroll
            for (int mt = 0; mt < 4; mt++)
#pragma unroll
                for (int nt = 0; nt < 4; nt++)
                    mma_bf16(acc[mt][nt], afr[mt], bfr[nt]);
        }
        __syncthreads();
    }

    // ---- normal epilogue ----
#pragma unroll
    for (int mt = 0; mt < 4; mt++) {
#pragma unroll
        for (int nt = 0; nt < 4; nt++) {
            int n0 = (int)colBase + warp_n * 32 + nt * 8 + (lane & 3) * 2;
            if (n0 >= Ntot) continue;
            long m0 = rowBase + warp_m * 64 + mt * 16 + (lane >> 2);
            float v0 = acc[mt][nt][0], v1 = acc[mt][nt][1];
            float v2 = acc[mt][nt][2], v3 = acc[mt][nt][3];
            if (gvec) {
                float ga = gvec[n0], gb = gvec[n0 + 1], ba = bvec[n0], bb = bvec[n0 + 1];
                v0 = lrelu(ga * (v0 * BNS) + ba); v1 = lrelu(gb * (v1 * BNS) + bb);
                v2 = lrelu(ga * (v2 * BNS) + ba); v3 = lrelu(gb * (v3 * BNS) + bb);
            }
            *(float2*)(C + m0 * ldc + n0)       = make_float2(v0, v1);
            *(float2*)(C + (m0 + 8) * ldc + n0) = make_float2(v2, v3);
        }
    }

    // ---- mirror epilogue (SYM, off-diagonal): write transposed tile ----
    if (SYM && blockIdx.x < blockIdx.y) {
        float* stage = (float*)sbuf;        // 80 KB available, need 64*133*4 B
        const int SST = 133;
#pragma unroll
        for (int p = 0; p < 2; p++) {
            __syncthreads();
            if (warp_m == p) {
#pragma unroll
                for (int mt = 0; mt < 4; mt++)
#pragma unroll
                    for (int nt = 0; nt < 4; nt++)
#pragma unroll
                        for (int v = 0; v < 4; v++) {
                            int r = mt * 16 + (lane >> 2) + ((v & 2) ? 8 : 0);
                            int c = warp_n * 32 + nt * 8 + (lane & 3) * 2 + (v & 1);
                            stage[r * SST + c] = acc[mt][nt][v];
                        }
            }
            __syncthreads();
#pragma unroll
            for (int n = wid * 16; n < wid * 16 + 16; n++) {
                float a = stage[(2 * lane) * SST + n];
                float b = stage[(2 * lane + 1) * SST + n];
                *(float2*)(C + (colBase + n) * (long)ldc + rowBase + p * 64 + 2 * lane)
                    = make_float2(a, b);
            }
        }
    }
}

// ------------------------- SIMT GEMM (layer-1 A/Ct, K=3) --------------------
__global__ __launch_bounds__(256)
void gemm_tn_kernel(const float* __restrict__ A, int lda,
                    const float* __restrict__ B, int ldb,
                    float* __restrict__ C, int ldc,
                    int M, int N, int K)
{
    __shared__ float As[64][17];
    __shared__ float Bs[64][17];
    int tx = threadIdx.x, ty = threadIdx.y;
    int tid = ty * 16 + tx;
    int rowBase = blockIdx.y * 64;
    int colBase = blockIdx.x * 64;
    float acc[4][4] = {};
    for (int kk = 0; kk < K; kk += 16) {
#pragma unroll
        for (int l = 0; l < 4; l++) {
            int e = tid + l * 256;
            int r = e >> 4, k = e & 15;
            As[r][k] = (kk + k < K) ? A[(long)(rowBase + r) * lda + kk + k] : 0.f;
            Bs[r][k] = (kk + k < K && colBase + r < N) ? B[(long)(colBase + r) * ldb + kk + k] : 0.f;
        }
        __syncthreads();
#pragma unroll
        for (int k = 0; k < 16; k++) {
            float a[4], b[4];
#pragma unroll
            for (int i = 0; i < 4; i++) a[i] = As[ty * 4 + i][k];
#pragma unroll
            for (int j = 0; j < 4; j++) b[j] = Bs[tx * 4 + j][k];
#pragma unroll
            for (int i = 0; i < 4; i++)
#pragma unroll
                for (int j = 0; j < 4; j++) acc[i][j] = fmaf(a[i], b[j], acc[i][j]);
        }
        __syncthreads();
    }
#pragma unroll
    for (int i = 0; i < 4; i++) {
        int rrow = rowBase + ty * 4 + i;
        if (rrow >= M) continue;
#pragma unroll
        for (int j = 0; j < 4; j++) {
            int col = colBase + tx * 4 + j;
            if (col >= N) continue;
            C[(long)rrow * ldc + col] = acc[i][j];
        }
    }
}

// ------------------------- layer-1 fused kNN (K=3, no D) --------------------
#define TPK_SEG 64     // 2048 / 32 lanes
__global__ __launch_bounds__(256)
void knn3_fused_kernel(const float* __restrict__ X, int* __restrict__ idxout)
{
    __shared__ float sX[NPTS], sY[NPTS], sZ[NPTS], sN[NPTS];
    int tid = threadIdx.x, wid = tid >> 5, lane = tid & 31;
    int b = blockIdx.y;
    const float* Xb = X + (long)b * NPTS * 3;

    for (int j = tid; j < NPTS; j += 256) {
        float x = Xb[j * 3], y = Xb[j * 3 + 1], z = Xb[j * 3 + 2];
        sX[j] = x; sY[j] = y; sZ[j] = z;
        float s = 0.f; s = fmaf(x, x, s); s = fmaf(y, y, s); s = fmaf(z, z, s);
        sN[j] = s;
    }
    __syncthreads();

    int i = blockIdx.x * 8 + wid;
    float xi = sX[i], yi = sY[i], zi = sZ[i], ni = sN[i];

    float vals[TPK_SEG];
#pragma unroll
    for (int t = 0; t < TPK_SEG; t++) {
        int j = lane + (t << 5);
        float d = 0.f;
        d = fmaf(xi, sX[j], d); d = fmaf(yi, sY[j], d); d = fmaf(zi, sZ[j], d);
        vals[t] = 2.f * d - ni - sN[j];
    }

    float lmax = vals[0]; int lt = 0;
#pragma unroll
    for (int t = 1; t < TPK_SEG; t++)
        if (vals[t] > lmax) { lmax = vals[t]; lt = t; }

    int* orow = idxout + ((long)b * NPTS + i) * KNN;
    for (int r = 0; r < KNN; r++) {
        float v = lmax;
        int   j = lane + (lt << 5);
#pragma unroll
        for (int d = 16; d; d >>= 1) {
            float ov = __shfl_xor_sync(0xffffffffu, v, d);
            int   oj = __shfl_xor_sync(0xffffffffu, j, d);
            if (ov > v || (ov == v && oj < j)) { v = ov; j = oj; }
        }
        if (lane == 0) orow[r] = j;
        if ((j & 31) == lane) {
            vals[j >> 5] = -1e30f;
            lmax = vals[0]; lt = 0;
#pragma unroll
            for (int t = 1; t < TPK_SEG; t++)
                if (vals[t] > lmax) { lmax = vals[t]; lt = t; }
        }
    }
}

// ------------------------- top-20 per row (layers 2-4) -----------------------
__global__ __launch_bounds__(256)
void topk_warp_kernel(const float* __restrict__ D, const float* __restrict__ xx,
                      int* __restrict__ idxout)
{
    int wid = threadIdx.x >> 5, lane = threadIdx.x & 31;
    int row = blockIdx.x * 8 + wid;
    int b = row >> 11, i = row & 2047;

    const float* Drow = D + (long)b * NPTS * NPTS + (long)i * NPTS;
    const float* xxb  = xx + b * NPTS;
    float xi = xxb[i];

    float vals[TPK_SEG];
#pragma unroll
    for (int t = 0; t < TPK_SEG; t++) {
        int j = lane + (t << 5);
        vals[t] = 2.f * Drow[j] - xi - xxb[j];
    }

    float lmax = vals[0]; int lt = 0;
#pragma unroll
    for (int t = 1; t < TPK_SEG; t++)
        if (vals[t] > lmax) { lmax = vals[t]; lt = t; }

    int* orow = idxout + row * KNN;
    for (int r = 0; r < KNN; r++) {
        float v = lmax;
        int   j = lane + (lt << 5);
#pragma unroll
        for (int d = 16; d; d >>= 1) {
            float ov = __shfl_xor_sync(0xffffffffu, v, d);
            int   oj = __shfl_xor_sync(0xffffffffu, j, d);
            if (ov > v || (ov == v && oj < j)) { v = ov; j = oj; }
        }
        if (lane == 0) orow[r] = j;
        if ((j & 31) == lane) {
            vals[j >> 5] = -1e30f;
            lmax = vals[0]; lt = 0;
#pragma unroll
            for (int t = 1; t < TPK_SEG; t++)
                if (vals[t] > lmax) { lmax = vals[t]; lt = t; }
        }
    }
}

// ------------------------- concat weights fp32 (layer-1 only) ----------------
__global__ void wcat_kernel(const float* __restrict__ W, int C, int O, float* __restrict__ Wc)
{
    int t = blockIdx.x * blockDim.x + threadIdx.x;
    if (t >= O * C) return;
    int o = t / C, c = t % C;
    float wa = W[o * 2 * C + c], wb = W[o * 2 * C + C + c];
    Wc[o * C + c] = wa;
    Wc[(O + o) * C + c] = wb - wa;
}

// ------------------------- neighbor aggregate (merged A|Ct) ------------------
__global__ void agg_kernel(const float* __restrict__ ACt,
                           const int* __restrict__ idx,
                           const float* __restrict__ gv, const float* __restrict__ bv,
                           int O, float* __restrict__ out, int ldout)
{
    int row = blockIdx.x;
    int b = row >> 11;
    int o = threadIdx.x;
    int ld = 2 * O;
    __shared__ int sidx[KNN];
    if (o < KNN) sidx[o] = idx[row * KNN + o];
    __syncthreads();
    float c  = ACt[(long)row * ld + O + o];
    float gg = gv[o], bb = bv[o];
    float m = -1e30f;
#pragma unroll
    for (int j = 0; j < KNN; j++) {
        float v = ACt[((long)(b << 11) + sidx[j]) * ld + o] + c;
        v = lrelu(gg * (v * BNS) + bb);
        m = fmaxf(m, v);
    }
    out[(long)row * ldout + o] = m;
}

// ------------------------- global pool ---------------------------------------
__global__ void hpart_kernel(const float* __restrict__ H, float* __restrict__ part)
{
    int b = blockIdx.x >> 4, c = blockIdx.x & 15;
    int o = threadIdx.x;
    float mx = -1e30f, sm = 0.f;
    int n0 = c * 128;
    for (int n = n0; n < n0 + 128; n++) {
        float v = H[((long)(b * NPTS + n)) * 1024 + o];
        mx = fmaxf(mx, v); sm += v;
    }
    part[(long)blockIdx.x * 2048 + o]        = mx;
    part[(long)blockIdx.x * 2048 + 1024 + o] = sm;
}
__global__ void hcombine_kernel(const float* __restrict__ part, float* __restrict__ feat)
{
    int b = blockIdx.x, o = threadIdx.x;
    float mx = -1e30f, sm = 0.f;
    for (int c = 0; c < 16; c++) {
        mx = fmaxf(mx, part[(long)(b * 16 + c) * 2048 + o]);
        sm += part[(long)(b * 16 + c) * 2048 + 1024 + o];
    }
    feat[b * 2048 + o]        = mx;
    feat[b * 2048 + 1024 + o] = sm * (1.f / 2048.f);
}

// ------------------------- small FC -------------------------------------------
__global__ void fc_kernel(const float* __restrict__ in, int K,
                          const float* __restrict__ W, const float* __restrict__ bias,
                          const float* __restrict__ gv, const float* __restrict__ bv,
                          float* __restrict__ out, int O, int doLrelu)
{
    int gw = (blockIdx.x * blockDim.x + threadIdx.x) >> 5;
    int lane = threadIdx.x & 31;
    if (gw >= BATCH * O) return;
    int b = gw / O, o = gw % O;
    float s = 0.f;
    for (int k = lane; k < K; k += 32) s += in[b * K + k] * W[o * K + k];
#pragma unroll
    for (int d = 16; d; d >>= 1) s += __shfl_down_sync(0xffffffffu, s, d);
    if (lane == 0) {
        if (bias) s += bias[o];
        if (gv)   s = gv[o] * (s * BNS) + bv[o];
        if (doLrelu) s = lrelu(s);
        out[b * O + o] = s;
    }
}

// ============================================================================
static void edge_layer_tc(const float* Xin, int lda, int C,
                          const float* W, const float* gv, const float* bv, int O,
                          float* outcol, int ldout,
                          float* dD, float* dxx, int* didx, float* dACt,
                          __nv_bfloat16* dA3, __nv_bfloat16* dB3, __nv_bfloat16* dB3w)
{
    int K3 = 3 * C;
    // fused: A3 + B3 + xx in one pass over X
    splitxx_kernel<<<NROWS * 32 / 256, 256>>>(Xin, lda, C, NROWS, dA3, dB3, dxx);
    // dist = X @ X^T, symmetric: lower-tri tiles only + mirrored writes
    tc_gemm_kernel<true><<<dim3(NPTS / 128, NPTS / 128, BATCH), 256, SMEM_TC>>>(
        dA3, K3, (long)NPTS * K3, dB3, K3, (long)NPTS * K3,
        dD, NPTS, (long)NPTS * NPTS, K3, NPTS, nullptr, nullptr);
    topk_warp_kernel<<<NROWS / 8, 256>>>(dD, dxx, didx);
    // [A | Ct] = X @ [Wa ; Wb-Wa]^T in ONE GEMM (N = 2*O)
    wcatsplit_kernel<<<(2 * O * C + 255) / 256, 256>>>(W, C, O, dB3w);
    tc_gemm_kernel<false><<<dim3((2 * O + 127) / 128, NROWS / 128, 1), 256, SMEM_TC>>>(
        dA3, K3, 0, dB3w, K3, 0, dACt, 2 * O, 0, K3, 2 * O, nullptr, nullptr);
    agg_kernel<<<NROWS, O>>>(dACt, didx, gv, bv, O, outcol, ldout);
}

extern "C" void kernel_launch(void* const* d_in, const int* in_sizes, int n_in,
                              void* d_out, int out_size)
{
    const float* x   = (const float*)d_in[0];
    const float* W1  = (const float*)d_in[1];
    const float* g1  = (const float*)d_in[2];
    const float* b1  = (const float*)d_in[3];
    const float* W2  = (const float*)d_in[4];
    const float* g2  = (const float*)d_in[5];
    const float* b2  = (const float*)d_in[6];
    const float* W3  = (const float*)d_in[7];
    const float* g3  = (const float*)d_in[8];
    const float* b3  = (const float*)d_in[9];
    const float* W4  = (const float*)d_in[10];
    const float* g4  = (const float*)d_in[11];
    const float* b4  = (const float*)d_in[12];
    const float* W5  = (const float*)d_in[13];
    const float* g5  = (const float*)d_in[14];
    const float* b5  = (const float*)d_in[15];
    const float* L1  = (const float*)d_in[16];
    const float* g6  = (const float*)d_in[17];
    const float* b6  = (const float*)d_in[18];
    const float* L2  = (const float*)d_in[19];
    const float* L2b = (const float*)d_in[20];
    const float* g7  = (const float*)d_in[21];
    const float* b7  = (const float*)d_in[22];
    const float* L3  = (const float*)d_in[23];
    const float* L3b = (const float*)d_in[24];
    float* out = (float*)d_out;

    float *dD, *dxx, *dACt, *dWc, *dXC, *dH, *dPart, *dFeat, *dFc1, *dFc2;
    int* didx;
    __nv_bfloat16 *dA3, *dB3, *dB3w;
    cudaGetSymbolAddress((void**)&dD,    g_D);
    cudaGetSymbolAddress((void**)&dxx,   g_xx);
    cudaGetSymbolAddress((void**)&didx,  g_idx);
    cudaGetSymbolAddress((void**)&dACt,  g_ACt);
    cudaGetSymbolAddress((void**)&dWc,   g_Wc);
    cudaGetSymbolAddress((void**)&dXC,   g_XC);
    cudaGetSymbolAddress((void**)&dH,    g_H);
    cudaGetSymbolAddress((void**)&dPart, g_hpart);
    cudaGetSymbolAddress((void**)&dFeat, g_feat);
    cudaGetSymbolAddress((void**)&dFc1,  g_fc1);
    cudaGetSymbolAddress((void**)&dFc2,  g_fc2);
    cudaGetSymbolAddress((void**)&dA3,   g_A3);
    cudaGetSymbolAddress((void**)&dB3,   g_B3);
    cudaGetSymbolAddress((void**)&dB3w,  g_B3w);

    // raise dynamic smem limit for the pipelined GEMM (host-side, not captured)
    cudaFuncSetAttribute(tc_gemm_kernel<true>,
                         cudaFuncAttributeMaxDynamicSharedMemorySize, SMEM_TC);
    cudaFuncSetAttribute(tc_gemm_kernel<false>,
                         cudaFuncAttributeMaxDynamicSharedMemorySize, SMEM_TC);

    // ---- layer 1 (K=3): fused kNN + tiny SIMT GEMM ----
    {
        knn3_fused_kernel<<<dim3(NPTS / 8, BATCH), 256>>>(x, didx);
        wcat_kernel<<<(64 * 3 + 255) / 256, 256>>>(W1, 3, 64, dWc);
        gemm_tn_kernel<<<dim3(2, NROWS / 64), dim3(16, 16)>>>(
            x, 3, dWc, 3, dACt, 128, NROWS, 128, 3);
        agg_kernel<<<NROWS, 64>>>(dACt, didx, g1, b1, 64, dXC + 0, 512);
    }

    // ---- layers 2-4: mma.sync path ----
    edge_layer_tc(dXC + 0,   512, 64,  W2, g2, b2,  64, dXC + 64,  512,
                  dD, dxx, didx, dACt, dA3, dB3, dB3w);
    edge_layer_tc(dXC + 64,  512, 64,  W3, g3, b3, 128, dXC + 128, 512,
                  dD, dxx, didx, dACt, dA3, dB3, dB3w);
    edge_layer_tc(dXC + 128, 512, 128, W4, g4, b4, 256, dXC + 256, 512,
                  dD, dxx, didx, dACt, dA3, dB3, dB3w);

    // ---- h = lrelu(bn(XC @ W5^T)) on tensor cores ----
    {
        splitxx_kernel<<<NROWS * 32 / 256, 256>>>(dXC, 512, 512, NROWS, dA3, nullptr, nullptr);
        splitxx_kernel<<<1024 * 32 / 256, 256>>>(W5, 512, 512, 1024, nullptr, dB3w, nullptr);
        tc_gemm_kernel<false><<<dim3(1024 / 128, NROWS / 128, 1), 256, SMEM_TC>>>(
            dA3, 1536, 0, dB3w, 1536, 0, dH, 1024, 0, 1536, 1024, g5, b5);
    }

    // ---- global pool + FC head ----
    hpart_kernel<<<BATCH * 16, 1024>>>(dH, dPart);
    hcombine_kernel<<<BATCH, 1024>>>(dPart, dFeat);
    fc_kernel<<<(BATCH * 512 * 32 + 255) / 256, 256>>>(dFeat, 2048, L1, nullptr, g6, b6, dFc1, 512, 1);
    fc_kernel<<<(BATCH * 256 * 32 + 255) / 256, 256>>>(dFc1,  512,  L2, L2b,    g7, b7, dFc2, 256, 1);
    fc_kernel<<<(BATCH * 10  * 32 + 255) / 256, 256>>>(dFc2,  256,  L3, L3b,    nullptr, nullptr, out, 10, 0);
}

// round 11
// speedup vs baseline: 1.0494x; 1.0156x over previous
#include <cuda_runtime.h>
#include <cuda_bf16.h>
#include <cstdint>
#include <math.h>

// ============================================================================
// DGCNN forward. K>=32 GEMMs use mma.sync bf16 (hi/lo split, fp32 acc):
//   A3 = [a_hi | a_lo | a_hi], B3 = [b_hi | b_hi | b_lo]  (K tripled)
//   => A3 . B3 = ah.bh + al.bh + ah.bl ~= fp32 exact (err ~2^-18)
// tc_gemm: 4-stage cp.async circular pipeline (80 KB dynamic smem).
// Dist GEMM exploits symmetry (lower-tri tiles + mirrored smem-transpose).
// W5 GEMM fuses bn+lrelu+global max/mean pooling (H never materialized).
// Layer-1 fully fused: kNN in smem; A/Ct computed inline in agg1 (K=3).
// Top-k: warp-per-row in registers, 20 x warp-argmax, no block barriers.
// ============================================================================

#define BATCH   8
#define NPTS    2048
#define NROWS   (BATCH * NPTS)     // 16384
#define KNN     20
static __device__ __forceinline__ float lrelu(float x) { return x > 0.f ? x : 0.2f * x; }
#define BNS 0.9999950000374997f    // 1/sqrt(1+1e-5)

// ------------------------- scratch (device globals) -------------------------
__device__ float g_D [(long)BATCH * NPTS * NPTS];   // 134 MB inner products
__device__ float g_xx [NROWS];
__device__ int   g_idx[NROWS * KNN];
__device__ float g_ACt[(long)NROWS * 512];          // [A | Ct] merged, ld=2*O
__device__ float g_XC [NROWS * 512];                // concat(x1,x2,x3,x4)
__device__ float g_hpart[BATCH * 16 * 2048];
__device__ float g_feat [BATCH * 2048];
__device__ float g_fc1  [BATCH * 512];
__device__ float g_fc2  [BATCH * 256];
__device__ __align__(128) __nv_bfloat16 g_A3 [(long)NROWS * 1536];  // hi|lo|hi
__device__ __align__(128) __nv_bfloat16 g_B3 [(long)NROWS * 1536];  // hi|hi|lo
__device__ __align__(128) __nv_bfloat16 g_B3w[1024 * 1536];

// ------------------------- PTX helpers --------------------------------------
__device__ __forceinline__ uint32_t smem_u32(const void* p) {
    uint32_t a;
    asm("{ .reg .u64 t; cvta.to.shared.u64 t, %1; cvt.u32.u64 %0, t; }" : "=r"(a) : "l"(p));
    return a;
}
__device__ __forceinline__ void cp_async16(uint32_t s, const void* g, int src_bytes) {
    asm volatile("cp.async.cg.shared.global [%0], [%1], 16, %2;"
                 :: "r"(s), "l"(g), "r"(src_bytes));
}
__device__ __forceinline__ void ldm_x4(uint32_t a, uint32_t& r0, uint32_t& r1,
                                       uint32_t& r2, uint32_t& r3) {
    asm volatile("ldmatrix.sync.aligned.m8n8.x4.shared.b16 {%0,%1,%2,%3}, [%4];"
                 : "=r"(r0), "=r"(r1), "=r"(r2), "=r"(r3) : "r"(a));
}
__device__ __forceinline__ void mma_bf16(float* c, const uint32_t* a, const uint32_t* b) {
    asm volatile("mma.sync.aligned.m16n8k16.row.col.f32.bf16.bf16.f32 "
                 "{%0,%1,%2,%3}, {%4,%5,%6,%7}, {%8,%9}, {%0,%1,%2,%3};"
                 : "+f"(c[0]), "+f"(c[1]), "+f"(c[2]), "+f"(c[3])
                 : "r"(a[0]), "r"(a[1]), "r"(a[2]), "r"(a[3]), "r"(b[0]), "r"(b[1]));
}

// ------------------------- fused split (+optional xx), warp per row ---------
__global__ void splitxx_kernel(const float* __restrict__ X, int lda, int K, int M,
                               __nv_bfloat16* __restrict__ A3,
                               __nv_bfloat16* __restrict__ B3,
                               float* __restrict__ xx)
{
    int w = (blockIdx.x * blockDim.x + threadIdx.x) >> 5;
    int lane = threadIdx.x & 31;
    if (w >= M) return;
    const float* row = X + (long)w * lda;
    long base = (long)w * (3 * K);
    float s = 0.f;
    for (int k = lane; k < K; k += 32) {
        float v = row[k];
        __nv_bfloat16 hi = __float2bfloat16(v);
        __nv_bfloat16 lo = __float2bfloat16(v - __bfloat162float(hi));
        if (A3) { A3[base + k] = hi; A3[base + K + k] = lo; A3[base + 2 * K + k] = hi; }
        if (B3) { B3[base + k] = hi; B3[base + K + k] = hi; B3[base + 2 * K + k] = lo; }
        s = fmaf(v, v, s);
    }
    if (xx) {
#pragma unroll
        for (int d = 16; d; d >>= 1) s += __shfl_xor_sync(0xffffffffu, s, d);
        if (lane == 0) xx[w] = s;
    }
}

// ------------------------- fused wcat + split (weights -> B3 triple) --------
__global__ void wcatsplit_kernel(const float* __restrict__ W, int C, int O,
                                 __nv_bfloat16* __restrict__ B3w)
{
    int t = blockIdx.x * blockDim.x + threadIdx.x;
    if (t >= 2 * O * C) return;
    int o = t / C, c = t % C;
    float v = (o < O) ? W[o * 2 * C + c]
                      : (W[(o - O) * 2 * C + C + c] - W[(o - O) * 2 * C + c]);
    __nv_bfloat16 hi = __float2bfloat16(v);
    __nv_bfloat16 lo = __float2bfloat16(v - __bfloat162float(hi));
    long base = (long)o * (3 * C);
    B3w[base + c] = hi; B3w[base + C + c] = hi; B3w[base + 2 * C + c] = lo;
}

// ------------------------- mma.sync GEMM  C = A3 @ B3^T ---------------------
// CTA tile 128x128, K-chunk 32, 4-stage cp.async circular pipeline.
// SYM: lower-tri tiles only; bx<by also writes the mirrored tile.
// POOL: bn+lrelu then per-CTA max/sum over 128 rows into part buffer
//       (C = part base; row tile must lie within one batch).
#define TPAD 40                 // bf16/row (32 data + 8 pad) -> 80 B stride
#define STAGE_B (2 * 128 * TPAD * 2)   // bytes per stage (A buf + B buf) = 20480
#define SMEM_TC (4 * STAGE_B)          // 81920

template<bool SYM, bool POOL>
__global__ __launch_bounds__(256)
void tc_gemm_kernel(const __nv_bfloat16* __restrict__ A, int lda, long sA,
                    const __nv_bfloat16* __restrict__ B, int ldb, long sB,
                    float* __restrict__ C, int ldc, long sC,
                    int K3, int Ntot,
                    const float* __restrict__ gvec, const float* __restrict__ bvec)
{
    if (SYM && blockIdx.x > blockIdx.y) return;

    extern __shared__ __align__(16) char sbuf[];

    int tid = threadIdx.x, wid = tid >> 5, lane = tid & 31;
    A += (long)blockIdx.z * sA; B += (long)blockIdx.z * sB; C += (long)blockIdx.z * sC;
    long rowBase = (long)blockIdx.y * 128;
    long colBase = (long)blockIdx.x * 128;

    int warp_m = wid & 1;
    int warp_n = wid >> 1;

    uint32_t smem0 = smem_u32(sbuf);
    int ldr0 = (tid * 2) >> 2,     lds0 = (tid * 2) & 3;
    int ldr1 = (tid * 2 + 1) >> 2, lds1 = (tid * 2 + 1) & 3;

    int nch = K3 >> 5;
    float acc[4][4][4] = {};

    int vb0 = (colBase + ldr0 < Ntot) ? 16 : 0;
    int vb1 = (colBase + ldr1 < Ntot) ? 16 : 0;

    // preload chunks 0..2
#pragma unroll
    for (int p = 0; p < 3; p++) {
        if (p < nch) {
            uint32_t sa = smem0 + p * STAGE_B;
            uint32_t sb = sa + 128 * TPAD * 2;
            const __nv_bfloat16* Ag = A + rowBase * lda + p * 32;
            const __nv_bfloat16* Bg = B + colBase * ldb + p * 32;
            cp_async16(sa + (ldr0 * TPAD + lds0 * 8) * 2, Ag + (long)ldr0 * lda + lds0 * 8, 16);
            cp_async16(sa + (ldr1 * TPAD + lds1 * 8) * 2, Ag + (long)ldr1 * lda + lds1 * 8, 16);
            cp_async16(sb + (ldr0 * TPAD + lds0 * 8) * 2, Bg + (long)ldr0 * ldb + lds0 * 8, vb0);
            cp_async16(sb + (ldr1 * TPAD + lds1 * 8) * 2, Bg + (long)ldr1 * ldb + lds1 * 8, vb1);
        }
        asm volatile("cp.async.commit_group;");
    }

    for (int ch = 0; ch < nch; ch++) {
        int nxt = ch + 3;
        if (nxt < nch) {
            int st = nxt & 3;
            uint32_t sa = smem0 + st * STAGE_B;
            uint32_t sb = sa + 128 * TPAD * 2;
            const __nv_bfloat16* Ag = A + rowBase * lda + nxt * 32;
            const __nv_bfloat16* Bg = B + colBase * ldb + nxt * 32;
            cp_async16(sa + (ldr0 * TPAD + lds0 * 8) * 2, Ag + (long)ldr0 * lda + lds0 * 8, 16);
            cp_async16(sa + (ldr1 * TPAD + lds1 * 8) * 2, Ag + (long)ldr1 * lda + lds1 * 8, 16);
            cp_async16(sb + (ldr0 * TPAD + lds0 * 8) * 2, Bg + (long)ldr0 * ldb + lds0 * 8, vb0);
            cp_async16(sb + (ldr1 * TPAD + lds1 * 8) * 2, Bg + (long)ldr1 * ldb + lds1 * 8, vb1);
            asm volatile("cp.async.commit_group;");
        }
        int rem = nch - 1 - ch;
        if (nxt < nch)      asm volatile("cp.async.wait_group 3;");
        else if (rem == 2)  asm volatile("cp.async.wait_group 2;");
        else if (rem == 1)  asm volatile("cp.async.wait_group 1;");
        else                asm volatile("cp.async.wait_group 0;");
        __syncthreads();

        int st = ch & 3;
        uint32_t sa_b = smem0 + st * STAGE_B;
        uint32_t sb_b = sa_b + 128 * TPAD * 2;

#pragma unroll
        for (int ks = 0; ks < 2; ks++) {
            uint32_t afr[4][4], bfr[4][2];
#pragma unroll
            for (int mt = 0; mt < 4; mt++) {
                int r = warp_m * 64 + mt * 16 + (lane & 15);
                int c = ks * 16 + (lane >> 4) * 8;
                ldm_x4(sa_b + (r * TPAD + c) * 2,
                       afr[mt][0], afr[mt][1], afr[mt][2], afr[mt][3]);
            }
#pragma unroll
            for (int np = 0; np < 2; np++) {
                int r = warp_n * 32 + np * 16 + (lane & 7) + ((lane & 16) >> 1);
                int c = ks * 16 + ((lane >> 3) & 1) * 8;
                uint32_t r0, r1, r2, r3;
                ldm_x4(sb_b + (r * TPAD + c) * 2, r0, r1, r2, r3);
                bfr[np * 2][0] = r0; bfr[np * 2][1] = r1;
                bfr[np * 2 + 1][0] = r2; bfr[np * 2 + 1][1] = r3;
            }
#pragma unroll
            for (int mt = 0; mt < 4; mt++)
#pragma unroll
                for (int nt = 0; nt < 4; nt++)
                    mma_bf16(acc[mt][nt], afr[mt], bfr[nt]);
        }
        __syncthreads();
    }

    // ---- bn + lrelu in registers (POOL path; normal path applies on store) --
    if (POOL) {
#pragma unroll
        for (int mt = 0; mt < 4; mt++)
#pragma unroll
            for (int nt = 0; nt < 4; nt++) {
                int n0 = (int)colBase + warp_n * 32 + nt * 8 + (lane & 3) * 2;
                float ga = gvec[n0], gb = gvec[n0 + 1], ba = bvec[n0], bb = bvec[n0 + 1];
                acc[mt][nt][0] = lrelu(ga * (acc[mt][nt][0] * BNS) + ba);
                acc[mt][nt][1] = lrelu(gb * (acc[mt][nt][1] * BNS) + bb);
                acc[mt][nt][2] = lrelu(ga * (acc[mt][nt][2] * BNS) + ba);
                acc[mt][nt][3] = lrelu(gb * (acc[mt][nt][3] * BNS) + bb);
            }
        // stage 64 rows per phase, reduce max/sum over all 128 rows per column
        float* stage = (float*)sbuf;
        const int SST = 132;
        int colL = tid >> 1, half = tid & 1;
        float mxA = -1e30f, smA = 0.f;
#pragma unroll
        for (int p = 0; p < 2; p++) {
            __syncthreads();
            if (warp_m == p) {
#pragma unroll
                for (int mt = 0; mt < 4; mt++)
#pragma unroll
                    for (int nt = 0; nt < 4; nt++)
#pragma unroll
                        for (int v = 0; v < 4; v++) {
                            int r = mt * 16 + (lane >> 2) + ((v & 2) ? 8 : 0);
                            int c = warp_n * 32 + nt * 8 + (lane & 3) * 2 + (v & 1);
                            stage[r * SST + c] = acc[mt][nt][v];
                        }
            }
            __syncthreads();
            float mx = -1e30f, sm = 0.f;
            for (int r = half * 32; r < half * 32 + 32; r++) {
                float v = stage[r * SST + colL];
                mx = fmaxf(mx, v); sm += v;
            }
            float omx = __shfl_xor_sync(0xffffffffu, mx, 1);
            float osm = __shfl_xor_sync(0xffffffffu, sm, 1);
            if (half == 0) { mx = fmaxf(mx, omx); sm += osm; }
            mxA = fmaxf(mxA, mx); smA += sm;
        }
        if (half == 0) {
            int b  = (int)(rowBase >> 11);
            int ct = (int)((rowBase & 2047) >> 7);
            long o = ((long)(b * 16 + ct)) * 2048;
            C[o + colBase + colL]        = mxA;
            C[o + 1024 + colBase + colL] = smA;
        }
        return;
    }

    // ---- normal epilogue ----
#pragma unroll
    for (int mt = 0; mt < 4; mt++) {
#pragma unroll
        for (int nt = 0; nt < 4; nt++) {
            int n0 = (int)colBase + warp_n * 32 + nt * 8 + (lane & 3) * 2;
            if (n0 >= Ntot) continue;
            long m0 = rowBase + warp_m * 64 + mt * 16 + (lane >> 2);
            float v0 = acc[mt][nt][0], v1 = acc[mt][nt][1];
            float v2 = acc[mt][nt][2], v3 = acc[mt][nt][3];
            if (gvec) {
                float ga = gvec[n0], gb = gvec[n0 + 1], ba = bvec[n0], bb = bvec[n0 + 1];
                v0 = lrelu(ga * (v0 * BNS) + ba); v1 = lrelu(gb * (v1 * BNS) + bb);
                v2 = lrelu(ga * (v2 * BNS) + ba); v3 = lrelu(gb * (v3 * BNS) + bb);
            }
            *(float2*)(C + m0 * ldc + n0)       = make_float2(v0, v1);
            *(float2*)(C + (m0 + 8) * ldc + n0) = make_float2(v2, v3);
        }
    }

    // ---- mirror epilogue (SYM, off-diagonal): write transposed tile ----
    if (SYM && blockIdx.x < blockIdx.y) {
        float* stage = (float*)sbuf;
        const int SST = 133;
#pragma unroll
        for (int p = 0; p < 2; p++) {
            __syncthreads();
            if (warp_m == p) {
#pragma unroll
                for (int mt = 0; mt < 4; mt++)
#pragma unroll
                    for (int nt = 0; nt < 4; nt++)
#pragma unroll
                        for (int v = 0; v < 4; v++) {
                            int r = mt * 16 + (lane >> 2) + ((v & 2) ? 8 : 0);
                            int c = warp_n * 32 + nt * 8 + (lane & 3) * 2 + (v & 1);
                            stage[r * SST + c] = acc[mt][nt][v];
                        }
            }
            __syncthreads();
#pragma unroll
            for (int n = wid * 16; n < wid * 16 + 16; n++) {
                float a = stage[(2 * lane) * SST + n];
                float b = stage[(2 * lane + 1) * SST + n];
                *(float2*)(C + (colBase + n) * (long)ldc + rowBase + p * 64 + 2 * lane)
                    = make_float2(a, b);
            }
        }
    }
}

// ------------------------- layer-1 fused kNN (K=3, no D) --------------------
#define TPK_SEG 64     // 2048 / 32 lanes
__global__ __launch_bounds__(256)
void knn3_fused_kernel(const float* __restrict__ X, int* __restrict__ idxout)
{
    __shared__ float sX[NPTS], sY[NPTS], sZ[NPTS], sN[NPTS];
    int tid = threadIdx.x, wid = tid >> 5, lane = tid & 31;
    int b = blockIdx.y;
    const float* Xb = X + (long)b * NPTS * 3;

    for (int j = tid; j < NPTS; j += 256) {
        float x = Xb[j * 3], y = Xb[j * 3 + 1], z = Xb[j * 3 + 2];
        sX[j] = x; sY[j] = y; sZ[j] = z;
        float s = 0.f; s = fmaf(x, x, s); s = fmaf(y, y, s); s = fmaf(z, z, s);
        sN[j] = s;
    }
    __syncthreads();

    int i = blockIdx.x * 8 + wid;
    float xi = sX[i], yi = sY[i], zi = sZ[i], ni = sN[i];

    float vals[TPK_SEG];
#pragma unroll
    for (int t = 0; t < TPK_SEG; t++) {
        int j = lane + (t << 5);
        float d = 0.f;
        d = fmaf(xi, sX[j], d); d = fmaf(yi, sY[j], d); d = fmaf(zi, sZ[j], d);
        vals[t] = 2.f * d - ni - sN[j];
    }

    float lmax = vals[0]; int lt = 0;
#pragma unroll
    for (int t = 1; t < TPK_SEG; t++)
        if (vals[t] > lmax) { lmax = vals[t]; lt = t; }

    int* orow = idxout + ((long)b * NPTS + i) * KNN;
    for (int r = 0; r < KNN; r++) {
        float v = lmax;
        int   j = lane + (lt << 5);
#pragma unroll
        for (int d = 16; d; d >>= 1) {
            float ov = __shfl_xor_sync(0xffffffffu, v, d);
            int   oj = __shfl_xor_sync(0xffffffffu, j, d);
            if (ov > v || (ov == v && oj < j)) { v = ov; j = oj; }
        }
        if (lane == 0) orow[r] = j;
        if ((j & 31) == lane) {
            vals[j >> 5] = -1e30f;
            lmax = vals[0]; lt = 0;
#pragma unroll
            for (int t = 1; t < TPK_SEG; t++)
                if (vals[t] > lmax) { lmax = vals[t]; lt = t; }
        }
    }
}

// ------------------------- layer-1 fused aggregate (K=3) ---------------------
__global__ void agg1_kernel(const float* __restrict__ X, const float* __restrict__ W1,
                            const int* __restrict__ idx,
                            const float* __restrict__ gv, const float* __restrict__ bv,
                            float* __restrict__ out, int ldout)
{
    int row = blockIdx.x;
    int b = row >> 11;
    int o = threadIdx.x;                 // 64
    __shared__ int   sidx[KNN];
    __shared__ float sxn[KNN][3];
    __shared__ float sxi[3];
    if (o < KNN) sidx[o] = idx[row * KNN + o];
    if (o < 3)   sxi[o]  = X[(long)row * 3 + o];
    __syncthreads();
    if (o < KNN) {
        long nr = (long)(b << 11) + sidx[o];
        sxn[o][0] = X[nr * 3]; sxn[o][1] = X[nr * 3 + 1]; sxn[o][2] = X[nr * 3 + 2];
    }
    __syncthreads();
    float wa0 = W1[o * 6],     wa1 = W1[o * 6 + 1], wa2 = W1[o * 6 + 2];
    float wd0 = W1[o * 6 + 3] - wa0, wd1 = W1[o * 6 + 4] - wa1, wd2 = W1[o * 6 + 5] - wa2;
    float ct = 0.f;
    ct = fmaf(wd0, sxi[0], ct); ct = fmaf(wd1, sxi[1], ct); ct = fmaf(wd2, sxi[2], ct);
    float gg = gv[o], bb = bv[o], m = -1e30f;
#pragma unroll
    for (int j = 0; j < KNN; j++) {
        float a = 0.f;
        a = fmaf(wa0, sxn[j][0], a); a = fmaf(wa1, sxn[j][1], a); a = fmaf(wa2, sxn[j][2], a);
        float v = a + ct;
        v = lrelu(gg * (v * BNS) + bb);
        m = fmaxf(m, v);
    }
    out[(long)row * ldout + o] = m;
}

// ------------------------- top-20 per row (layers 2-4) -----------------------
__global__ __launch_bounds__(256)
void topk_warp_kernel(const float* __restrict__ D, const float* __restrict__ xx,
                      int* __restrict__ idxout)
{
    int wid = threadIdx.x >> 5, lane = threadIdx.x & 31;
    int row = blockIdx.x * 8 + wid;
    int b = row >> 11, i = row & 2047;

    const float* Drow = D + (long)b * NPTS * NPTS + (long)i * NPTS;
    const float* xxb  = xx + b * NPTS;
    float xi = xxb[i];

    float vals[TPK_SEG];
#pragma unroll
    for (int t = 0; t < TPK_SEG; t++) {
        int j = lane + (t << 5);
        vals[t] = 2.f * Drow[j] - xi - xxb[j];
    }

    float lmax = vals[0]; int lt = 0;
#pragma unroll
    for (int t = 1; t < TPK_SEG; t++)
        if (vals[t] > lmax) { lmax = vals[t]; lt = t; }

    int* orow = idxout + row * KNN;
    for (int r = 0; r < KNN; r++) {
        float v = lmax;
        int   j = lane + (lt << 5);
#pragma unroll
        for (int d = 16; d; d >>= 1) {
            float ov = __shfl_xor_sync(0xffffffffu, v, d);
            int   oj = __shfl_xor_sync(0xffffffffu, j, d);
            if (ov > v || (ov == v && oj < j)) { v = ov; j = oj; }
        }
        if (lane == 0) orow[r] = j;
        if ((j & 31) == lane) {
            vals[j >> 5] = -1e30f;
            lmax = vals[0]; lt = 0;
#pragma unroll
            for (int t = 1; t < TPK_SEG; t++)
                if (vals[t] > lmax) { lmax = vals[t]; lt = t; }
        }
    }
}

// ------------------------- neighbor aggregate (merged A|Ct) ------------------
__global__ void agg_kernel(const float* __restrict__ ACt,
                           const int* __restrict__ idx,
                           const float* __restrict__ gv, const float* __restrict__ bv,
                           int O, float* __restrict__ out, int ldout)
{
    int row = blockIdx.x;
    int b = row >> 11;
    int o = threadIdx.x;
    int ld = 2 * O;
    __shared__ int sidx[KNN];
    if (o < KNN) sidx[o] = idx[row * KNN + o];
    __syncthreads();
    float c  = ACt[(long)row * ld + O + o];
    float gg = gv[o], bb = bv[o];
    float m = -1e30f;
#pragma unroll
    for (int j = 0; j < KNN; j++) {
        float v = ACt[((long)(b << 11) + sidx[j]) * ld + o] + c;
        v = lrelu(gg * (v * BNS) + bb);
        m = fmaxf(m, v);
    }
    out[(long)row * ldout + o] = m;
}

// ------------------------- pool combine --------------------------------------
__global__ void hcombine_kernel(const float* __restrict__ part, float* __restrict__ feat)
{
    int b = blockIdx.x, o = threadIdx.x;
    float mx = -1e30f, sm = 0.f;
    for (int c = 0; c < 16; c++) {
        mx = fmaxf(mx, part[(long)(b * 16 + c) * 2048 + o]);
        sm += part[(long)(b * 16 + c) * 2048 + 1024 + o];
    }
    feat[b * 2048 + o]        = mx;
    feat[b * 2048 + 1024 + o] = sm * (1.f / 2048.f);
}

// ------------------------- small FC -------------------------------------------
__global__ void fc_kernel(const float* __restrict__ in, int K,
                          const float* __restrict__ W, const float* __restrict__ bias,
                          const float* __restrict__ gv, const float* __restrict__ bv,
                          float* __restrict__ out, int O, int doLrelu)
{
    int gw = (blockIdx.x * blockDim.x + threadIdx.x) >> 5;
    int lane = threadIdx.x & 31;
    if (gw >= BATCH * O) return;
    int b = gw / O, o = gw % O;
    float s = 0.f;
    for (int k = lane; k < K; k += 32) s += in[b * K + k] * W[o * K + k];
#pragma unroll
    for (int d = 16; d; d >>= 1) s += __shfl_down_sync(0xffffffffu, s, d);
    if (lane == 0) {
        if (bias) s += bias[o];
        if (gv)   s = gv[o] * (s * BNS) + bv[o];
        if (doLrelu) s = lrelu(s);
        out[b * O + o] = s;
    }
}

// ============================================================================
static void edge_layer_tc(const float* Xin, int lda, int C,
                          const float* W, const float* gv, const float* bv, int O,
                          float* outcol, int ldout,
                          float* dD, float* dxx, int* didx, float* dACt,
                          __nv_bfloat16* dA3, __nv_bfloat16* dB3, __nv_bfloat16* dB3w)
{
    int K3 = 3 * C;
    splitxx_kernel<<<NROWS * 32 / 256, 256>>>(Xin, lda, C, NROWS, dA3, dB3, dxx);
    tc_gemm_kernel<true, false><<<dim3(NPTS / 128, NPTS / 128, BATCH), 256, SMEM_TC>>>(
        dA3, K3, (long)NPTS * K3, dB3, K3, (long)NPTS * K3,
        dD, NPTS, (long)NPTS * NPTS, K3, NPTS, nullptr, nullptr);
    topk_warp_kernel<<<NROWS / 8, 256>>>(dD, dxx, didx);
    wcatsplit_kernel<<<(2 * O * C + 255) / 256, 256>>>(W, C, O, dB3w);
    tc_gemm_kernel<false, false><<<dim3((2 * O + 127) / 128, NROWS / 128, 1), 256, SMEM_TC>>>(
        dA3, K3, 0, dB3w, K3, 0, dACt, 2 * O, 0, K3, 2 * O, nullptr, nullptr);
    agg_kernel<<<NROWS, O>>>(dACt, didx, gv, bv, O, outcol, ldout);
}

extern "C" void kernel_launch(void* const* d_in, const int* in_sizes, int n_in,
                              void* d_out, int out_size)
{
    const float* x   = (const float*)d_in[0];
    const float* W1  = (const float*)d_in[1];
    const float* g1  = (const float*)d_in[2];
    const float* b1  = (const float*)d_in[3];
    const float* W2  = (const float*)d_in[4];
    const float* g2  = (const float*)d_in[5];
    const float* b2  = (const float*)d_in[6];
    const float* W3  = (const float*)d_in[7];
    const float* g3  = (const float*)d_in[8];
    const float* b3  = (const float*)d_in[9];
    const float* W4  = (const float*)d_in[10];
    const float* g4  = (const float*)d_in[11];
    const float* b4  = (const float*)d_in[12];
    const float* W5  = (const float*)d_in[13];
    const float* g5  = (const float*)d_in[14];
    const float* b5  = (const float*)d_in[15];
    const float* L1  = (const float*)d_in[16];
    const float* g6  = (const float*)d_in[17];
    const float* b6  = (const float*)d_in[18];
    const float* L2  = (const float*)d_in[19];
    const float* L2b = (const float*)d_in[20];
    const float* g7  = (const float*)d_in[21];
    const float* b7  = (const float*)d_in[22];
    const float* L3  = (const float*)d_in[23];
    const float* L3b = (const float*)d_in[24];
    float* out = (float*)d_out;

    float *dD, *dxx, *dACt, *dXC, *dPart, *dFeat, *dFc1, *dFc2;
    int* didx;
    __nv_bfloat16 *dA3, *dB3, *dB3w;
    cudaGetSymbolAddress((void**)&dD,    g_D);
    cudaGetSymbolAddress((void**)&dxx,   g_xx);
    cudaGetSymbolAddress((void**)&didx,  g_idx);
    cudaGetSymbolAddress((void**)&dACt,  g_ACt);
    cudaGetSymbolAddress((void**)&dXC,   g_XC);
    cudaGetSymbolAddress((void**)&dPart, g_hpart);
    cudaGetSymbolAddress((void**)&dFeat, g_feat);
    cudaGetSymbolAddress((void**)&dFc1,  g_fc1);
    cudaGetSymbolAddress((void**)&dFc2,  g_fc2);
    cudaGetSymbolAddress((void**)&dA3,   g_A3);
    cudaGetSymbolAddress((void**)&dB3,   g_B3);
    cudaGetSymbolAddress((void**)&dB3w,  g_B3w);

    // raise dynamic smem limit for the pipelined GEMM (host-side, not captured)
    cudaFuncSetAttribute(tc_gemm_kernel<true, false>,
                         cudaFuncAttributeMaxDynamicSharedMemorySize, SMEM_TC);
    cudaFuncSetAttribute(tc_gemm_kernel<false, false>,
                         cudaFuncAttributeMaxDynamicSharedMemorySize, SMEM_TC);
    cudaFuncSetAttribute(tc_gemm_kernel<false, true>,
                         cudaFuncAttributeMaxDynamicSharedMemorySize, SMEM_TC);

    // ---- layer 1 (K=3): fused kNN + fused A/Ct aggregate ----
    knn3_fused_kernel<<<dim3(NPTS / 8, BATCH), 256>>>(x, didx);
    agg1_kernel<<<NROWS, 64>>>(x, W1, didx, g1, b1, dXC + 0, 512);

    // ---- layers 2-4: mma.sync path ----
    edge_layer_tc(dXC + 0,   512, 64,  W2, g2, b2,  64, dXC + 64,  512,
                  dD, dxx, didx, dACt, dA3, dB3, dB3w);
    edge_layer_tc(dXC + 64,  512, 64,  W3, g3, b3, 128, dXC + 128, 512,
                  dD, dxx, didx, dACt, dA3, dB3, dB3w);
    edge_layer_tc(dXC + 128, 512, 128, W4, g4, b4, 256, dXC + 256, 512,
                  dD, dxx, didx, dACt, dA3, dB3, dB3w);

    // ---- h = lrelu(bn(XC @ W5^T)) fused with global max/mean pooling ----
    {
        splitxx_kernel<<<NROWS * 32 / 256, 256>>>(dXC, 512, 512, NROWS, dA3, nullptr, nullptr);
        splitxx_kernel<<<1024 * 32 / 256, 256>>>(W5, 512, 512, 1024, nullptr, dB3w, nullptr);
        tc_gemm_kernel<false, true><<<dim3(1024 / 128, NROWS / 128, 1), 256, SMEM_TC>>>(
            dA3, 1536, 0, dB3w, 1536, 0, dPart, 0, 0, 1536, 1024, g5, b5);
    }

    // ---- pool combine + FC head ----
    hcombine_kernel<<<BATCH, 1024>>>(dPart, dFeat);
    fc_kernel<<<(BATCH * 512 * 32 + 255) / 256, 256>>>(dFeat, 2048, L1, nullptr, g6, b6, dFc1, 512, 1);
    fc_kernel<<<(BATCH * 256 * 32 + 255) / 256, 256>>>(dFc1,  512,  L2, L2b,    g7, b7, dFc2, 256, 1);
    fc_kernel<<<(BATCH * 10  * 32 + 255) / 256, 256>>>(dFc2,  256,  L3, L3b,    nullptr, nullptr, out, 10, 0);
}

// round 12
// speedup vs baseline: 1.0658x; 1.0156x over previous
#include <cuda_runtime.h>
#include <cuda_bf16.h>
#include <cstdint>
#include <math.h>

// ============================================================================
// DGCNN forward. K>=32 GEMMs use mma.sync bf16 (hi/lo split, fp32 acc):
//   A3 = [a_hi | a_lo | a_hi], B3 = [b_hi | b_hi | b_lo]  (K tripled)
//   => A3 . B3 = ah.bh + al.bh + ah.bl ~= fp32 exact (err ~2^-18)
// tc_gemm: 4-stage cp.async circular pipeline (80 KB dynamic smem).
// Dist GEMM exploits symmetry (lower-tri tiles + mirrored smem-transpose);
// the otherwise-idle upper-tri CTAs execute the [A|Ct] GEMM in-launch.
// W5 GEMM fuses bn+lrelu+global max/mean pooling (H never materialized).
// Layer-1 fully fused: kNN in smem; A/Ct computed inline in agg1 (K=3).
// Top-k: warp-per-row in registers, 20 x warp-argmax, no block barriers.
// ============================================================================

#define BATCH   8
#define NPTS    2048
#define NROWS   (BATCH * NPTS)     // 16384
#define KNN     20
static __device__ __forceinline__ float lrelu(float x) { return x > 0.f ? x : 0.2f * x; }
#define BNS 0.9999950000374997f    // 1/sqrt(1+1e-5)

// ------------------------- scratch (device globals) -------------------------
__device__ float g_D [(long)BATCH * NPTS * NPTS];   // 134 MB inner products
__device__ float g_xx [NROWS];
__device__ int   g_idx[NROWS * KNN];
__device__ float g_ACt[(long)NROWS * 512];          // [A | Ct] merged, ld=2*O
__device__ float g_XC [NROWS * 512];                // concat(x1,x2,x3,x4)
__device__ float g_hpart[BATCH * 16 * 2048];
__device__ float g_feat [BATCH * 2048];
__device__ float g_fc1  [BATCH * 512];
__device__ float g_fc2  [BATCH * 256];
__device__ __align__(128) __nv_bfloat16 g_A3 [(long)NROWS * 1536];  // hi|lo|hi
__device__ __align__(128) __nv_bfloat16 g_B3 [(long)NROWS * 1536];  // hi|hi|lo
__device__ __align__(128) __nv_bfloat16 g_B3w[1024 * 1536];

// ------------------------- PTX helpers --------------------------------------
__device__ __forceinline__ uint32_t smem_u32(const void* p) {
    uint32_t a;
    asm("{ .reg .u64 t; cvta.to.shared.u64 t, %1; cvt.u32.u64 %0, t; }" : "=r"(a) : "l"(p));
    return a;
}
__device__ __forceinline__ void cp_async16(uint32_t s, const void* g, int src_bytes) {
    asm volatile("cp.async.cg.shared.global [%0], [%1], 16, %2;"
                 :: "r"(s), "l"(g), "r"(src_bytes));
}
__device__ __forceinline__ void ldm_x4(uint32_t a, uint32_t& r0, uint32_t& r1,
                                       uint32_t& r2, uint32_t& r3) {
    asm volatile("ldmatrix.sync.aligned.m8n8.x4.shared.b16 {%0,%1,%2,%3}, [%4];"
                 : "=r"(r0), "=r"(r1), "=r"(r2), "=r"(r3) : "r"(a));
}
__device__ __forceinline__ void mma_bf16(float* c, const uint32_t* a, const uint32_t* b) {
    asm volatile("mma.sync.aligned.m16n8k16.row.col.f32.bf16.bf16.f32 "
                 "{%0,%1,%2,%3}, {%4,%5,%6,%7}, {%8,%9}, {%0,%1,%2,%3};"
                 : "+f"(c[0]), "+f"(c[1]), "+f"(c[2]), "+f"(c[3])
                 : "r"(a[0]), "r"(a[1]), "r"(a[2]), "r"(a[3]), "r"(b[0]), "r"(b[1]));
}

// ------------------------- fused split (+optional xx), warp per row ---------
__global__ void splitxx_kernel(const float* __restrict__ X, int lda, int K, int M,
                               __nv_bfloat16* __restrict__ A3,
                               __nv_bfloat16* __restrict__ B3,
                               float* __restrict__ xx)
{
    int w = (blockIdx.x * blockDim.x + threadIdx.x) >> 5;
    int lane = threadIdx.x & 31;
    if (w >= M) return;
    const float* row = X + (long)w * lda;
    long base = (long)w * (3 * K);
    float s = 0.f;
    for (int k = lane; k < K; k += 32) {
        float v = row[k];
        __nv_bfloat16 hi = __float2bfloat16(v);
        __nv_bfloat16 lo = __float2bfloat16(v - __bfloat162float(hi));
        if (A3) { A3[base + k] = hi; A3[base + K + k] = lo; A3[base + 2 * K + k] = hi; }
        if (B3) { B3[base + k] = hi; B3[base + K + k] = hi; B3[base + 2 * K + k] = lo; }
        s = fmaf(v, v, s);
    }
    if (xx) {
#pragma unroll
        for (int d = 16; d; d >>= 1) s += __shfl_xor_sync(0xffffffffu, s, d);
        if (lane == 0) xx[w] = s;
    }
}

// ------------------------- fused wcat + split (weights -> B3 triple) --------
__global__ void wcatsplit_kernel(const float* __restrict__ W, int C, int O,
                                 __nv_bfloat16* __restrict__ B3w)
{
    int t = blockIdx.x * blockDim.x + threadIdx.x;
    if (t >= 2 * O * C) return;
    int o = t / C, c = t % C;
    float v = (o < O) ? W[o * 2 * C + c]
                      : (W[(o - O) * 2 * C + C + c] - W[(o - O) * 2 * C + c]);
    __nv_bfloat16 hi = __float2bfloat16(v);
    __nv_bfloat16 lo = __float2bfloat16(v - __bfloat162float(hi));
    long base = (long)o * (3 * C);
    B3w[base + c] = hi; B3w[base + C + c] = hi; B3w[base + 2 * C + c] = lo;
}

// ------------------------- mma.sync GEMM  C = A3 @ B3^T ---------------------
// CTA tile 128x128, K-chunk 32, 4-stage cp.async circular pipeline.
// SYM: lower-tri tiles compute D (+ mirrored writes); upper-tri CTAs are
//      recycled to run the secondary GEMM (A3 @ B2^T -> C2, n2x*128 cols).
// POOL: bn+lrelu then per-CTA max/sum over 128 rows into part buffer.
#define TPAD 40                 // bf16/row (32 data + 8 pad) -> 80 B stride
#define STAGE_B (2 * 128 * TPAD * 2)   // bytes per stage (A buf + B buf) = 20480
#define SMEM_TC (4 * STAGE_B)          // 81920

template<bool SYM, bool POOL>
__global__ __launch_bounds__(256)
void tc_gemm_kernel(const __nv_bfloat16* __restrict__ A, int lda, long sA,
                    const __nv_bfloat16* __restrict__ B, int ldb, long sB,
                    float* __restrict__ C, int ldc, long sC,
                    int K3, int Ntot,
                    const float* __restrict__ gvec, const float* __restrict__ bvec,
                    const __nv_bfloat16* __restrict__ B2, float* __restrict__ C2,
                    int ldc2, int n2x)
{
    extern __shared__ __align__(16) char sbuf[];

    int tid = threadIdx.x, wid = tid >> 5, lane = tid & 31;
    long rowBase, colBase;
    bool act = false;

    if (SYM && blockIdx.x > blockIdx.y) {
        // recycled CTA: secondary GEMM tile
        if (B2 == nullptr) return;
        int nx = gridDim.x;
        int bx = blockIdx.x, by = blockIdx.y;
        int upp = by * (nx - 1) - (by * (by - 1)) / 2 + (bx - by - 1);
        int id = blockIdx.z * ((nx * (nx - 1)) / 2) + upp;
        if (id >= n2x * 128) return;
        act = true;
        rowBase = (long)(id % 128) * 128;   // global M-rows
        colBase = (long)(id / 128) * 128;
        B = B2; C = C2; ldc = ldc2;
    } else {
        A += (long)blockIdx.z * sA; B += (long)blockIdx.z * sB; C += (long)blockIdx.z * sC;
        rowBase = (long)blockIdx.y * 128;
        colBase = (long)blockIdx.x * 128;
    }

    int warp_m = wid & 1;
    int warp_n = wid >> 1;

    uint32_t smem0 = smem_u32(sbuf);
    int ldr0 = (tid * 2) >> 2,     lds0 = (tid * 2) & 3;
    int ldr1 = (tid * 2 + 1) >> 2, lds1 = (tid * 2 + 1) & 3;

    int nch = K3 >> 5;
    float acc[4][4][4] = {};

    // preload chunks 0..2
#pragma unroll
    for (int p = 0; p < 3; p++) {
        if (p < nch) {
            uint32_t sa = smem0 + p * STAGE_B;
            uint32_t sb = sa + 128 * TPAD * 2;
            const __nv_bfloat16* Ag = A + rowBase * lda + p * 32;
            const __nv_bfloat16* Bg = B + colBase * ldb + p * 32;
            cp_async16(sa + (ldr0 * TPAD + lds0 * 8) * 2, Ag + (long)ldr0 * lda + lds0 * 8, 16);
            cp_async16(sa + (ldr1 * TPAD + lds1 * 8) * 2, Ag + (long)ldr1 * lda + lds1 * 8, 16);
            cp_async16(sb + (ldr0 * TPAD + lds0 * 8) * 2, Bg + (long)ldr0 * ldb + lds0 * 8, 16);
            cp_async16(sb + (ldr1 * TPAD + lds1 * 8) * 2, Bg + (long)ldr1 * ldb + lds1 * 8, 16);
        }
        asm volatile("cp.async.commit_group;");
    }

    for (int ch = 0; ch < nch; ch++) {
        int nxt = ch + 3;
        if (nxt < nch) {
            int st = nxt & 3;
            uint32_t sa = smem0 + st * STAGE_B;
            uint32_t sb = sa + 128 * TPAD * 2;
            const __nv_bfloat16* Ag = A + rowBase * lda + nxt * 32;
            const __nv_bfloat16* Bg = B + colBase * ldb + nxt * 32;
            cp_async16(sa + (ldr0 * TPAD + lds0 * 8) * 2, Ag + (long)ldr0 * lda + lds0 * 8, 16);
            cp_async16(sa + (ldr1 * TPAD + lds1 * 8) * 2, Ag + (long)ldr1 * lda + lds1 * 8, 16);
            cp_async16(sb + (ldr0 * TPAD + lds0 * 8) * 2, Bg + (long)ldr0 * ldb + lds0 * 8, 16);
            cp_async16(sb + (ldr1 * TPAD + lds1 * 8) * 2, Bg + (long)ldr1 * ldb + lds1 * 8, 16);
            asm volatile("cp.async.commit_group;");
        }
        int rem = nch - 1 - ch;
        if (nxt < nch)      asm volatile("cp.async.wait_group 3;");
        else if (rem == 2)  asm volatile("cp.async.wait_group 2;");
        else if (rem == 1)  asm volatile("cp.async.wait_group 1;");
        else                asm volatile("cp.async.wait_group 0;");
        __syncthreads();

        int st = ch & 3;
        uint32_t sa_b = smem0 + st * STAGE_B;
        uint32_t sb_b = sa_b + 128 * TPAD * 2;

#pragma unroll
        for (int ks = 0; ks < 2; ks++) {
            uint32_t afr[4][4], bfr[4][2];
#pragma unroll
            for (int mt = 0; mt < 4; mt++) {
                int r = warp_m * 64 + mt * 16 + (lane & 15);
                int c = ks * 16 + (lane >> 4) * 8;
                ldm_x4(sa_b + (r * TPAD + c) * 2,
                       afr[mt][0], afr[mt][1], afr[mt][2], afr[mt][3]);
            }
#pragma unroll
            for (int np = 0; np < 2; np++) {
                int r = warp_n * 32 + np * 16 + (lane & 7) + ((lane & 16) >> 1);
                int c = ks * 16 + ((lane >> 3) & 1) * 8;
                uint32_t r0, r1, r2, r3;
                ldm_x4(sb_b + (r * TPAD + c) * 2, r0, r1, r2, r3);
                bfr[np * 2][0] = r0; bfr[np * 2][1] = r1;
                bfr[np * 2 + 1][0] = r2; bfr[np * 2 + 1][1] = r3;
            }
#pragma unroll
            for (int mt = 0; mt < 4; mt++)
#pragma unroll
                for (int nt = 0; nt < 4; nt++)
                    mma_bf16(acc[mt][nt], afr[mt], bfr[nt]);
        }
        __syncthreads();
    }

    // ---- bn + lrelu + pool epilogue ----
    if (POOL) {
#pragma unroll
        for (int mt = 0; mt < 4; mt++)
#pragma unroll
            for (int nt = 0; nt < 4; nt++) {
                int n0 = (int)colBase + warp_n * 32 + nt * 8 + (lane & 3) * 2;
                float ga = gvec[n0], gb = gvec[n0 + 1], ba = bvec[n0], bb = bvec[n0 + 1];
                acc[mt][nt][0] = lrelu(ga * (acc[mt][nt][0] * BNS) + ba);
                acc[mt][nt][1] = lrelu(gb * (acc[mt][nt][1] * BNS) + bb);
                acc[mt][nt][2] = lrelu(ga * (acc[mt][nt][2] * BNS) + ba);
                acc[mt][nt][3] = lrelu(gb * (acc[mt][nt][3] * BNS) + bb);
            }
        float* stage = (float*)sbuf;
        const int SST = 132;
        int colL = tid >> 1, half = tid & 1;
        float mxA = -1e30f, smA = 0.f;
#pragma unroll
        for (int p = 0; p < 2; p++) {
            __syncthreads();
            if (warp_m == p) {
#pragma unroll
                for (int mt = 0; mt < 4; mt++)
#pragma unroll
                    for (int nt = 0; nt < 4; nt++)
#pragma unroll
                        for (int v = 0; v < 4; v++) {
                            int r = mt * 16 + (lane >> 2) + ((v & 2) ? 8 : 0);
                            int c = warp_n * 32 + nt * 8 + (lane & 3) * 2 + (v & 1);
                            stage[r * SST + c] = acc[mt][nt][v];
                        }
            }
            __syncthreads();
            float mx = -1e30f, sm = 0.f;
            for (int r = half * 32; r < half * 32 + 32; r++) {
                float v = stage[r * SST + colL];
                mx = fmaxf(mx, v); sm += v;
            }
            float omx = __shfl_xor_sync(0xffffffffu, mx, 1);
            float osm = __shfl_xor_sync(0xffffffffu, sm, 1);
            if (half == 0) { mx = fmaxf(mx, omx); sm += osm; }
            mxA = fmaxf(mxA, mx); smA += sm;
        }
        if (half == 0) {
            int b  = (int)(rowBase >> 11);
            int ct = (int)((rowBase & 2047) >> 7);
            long o = ((long)(b * 16 + ct)) * 2048;
            C[o + colBase + colL]        = mxA;
            C[o + 1024 + colBase + colL] = smA;
        }
        return;
    }

    // ---- normal epilogue (dist lower-tri, or recycled-act tile) ----
#pragma unroll
    for (int mt = 0; mt < 4; mt++) {
#pragma unroll
        for (int nt = 0; nt < 4; nt++) {
            int n0 = (int)colBase + warp_n * 32 + nt * 8 + (lane & 3) * 2;
            if (n0 >= Ntot && !act) continue;
            long m0 = rowBase + warp_m * 64 + mt * 16 + (lane >> 2);
            float v0 = acc[mt][nt][0], v1 = acc[mt][nt][1];
            float v2 = acc[mt][nt][2], v3 = acc[mt][nt][3];
            if (!act && gvec) {
                float ga = gvec[n0], gb = gvec[n0 + 1], ba = bvec[n0], bb = bvec[n0 + 1];
                v0 = lrelu(ga * (v0 * BNS) + ba); v1 = lrelu(gb * (v1 * BNS) + bb);
                v2 = lrelu(ga * (v2 * BNS) + ba); v3 = lrelu(gb * (v3 * BNS) + bb);
            }
            *(float2*)(C + m0 * ldc + n0)       = make_float2(v0, v1);
            *(float2*)(C + (m0 + 8) * ldc + n0) = make_float2(v2, v3);
        }
    }

    // ---- mirror epilogue (SYM, off-diagonal dist): write transposed tile ----
    if (SYM && !act && blockIdx.x < blockIdx.y) {
        float* stage = (float*)sbuf;
        const int SST = 133;
#pragma unroll
        for (int p = 0; p < 2; p++) {
            __syncthreads();
            if (warp_m == p) {
#pragma unroll
                for (int mt = 0; mt < 4; mt++)
#pragma unroll
                    for (int nt = 0; nt < 4; nt++)
#pragma unroll
                        for (int v = 0; v < 4; v++) {
                            int r = mt * 16 + (lane >> 2) + ((v & 2) ? 8 : 0);
                            int c = warp_n * 32 + nt * 8 + (lane & 3) * 2 + (v & 1);
                            stage[r * SST + c] = acc[mt][nt][v];
                        }
            }
            __syncthreads();
#pragma unroll
            for (int n = wid * 16; n < wid * 16 + 16; n++) {
                float a = stage[(2 * lane) * SST + n];
                float b = stage[(2 * lane + 1) * SST + n];
                *(float2*)(C + (colBase + n) * (long)ldc + rowBase + p * 64 + 2 * lane)
                    = make_float2(a, b);
            }
        }
    }
}

// ------------------------- layer-1 fused kNN (K=3, no D) --------------------
#define TPK_SEG 64     // 2048 / 32 lanes
__global__ __launch_bounds__(256)
void knn3_fused_kernel(const float* __restrict__ X, int* __restrict__ idxout)
{
    __shared__ float sX[NPTS], sY[NPTS], sZ[NPTS], sN[NPTS];
    int tid = threadIdx.x, wid = tid >> 5, lane = tid & 31;
    int b = blockIdx.y;
    const float* Xb = X + (long)b * NPTS * 3;

    for (int j = tid; j < NPTS; j += 256) {
        float x = Xb[j * 3], y = Xb[j * 3 + 1], z = Xb[j * 3 + 2];
        sX[j] = x; sY[j] = y; sZ[j] = z;
        float s = 0.f; s = fmaf(x, x, s); s = fmaf(y, y, s); s = fmaf(z, z, s);
        sN[j] = s;
    }
    __syncthreads();

    int i = blockIdx.x * 8 + wid;
    float xi = sX[i], yi = sY[i], zi = sZ[i], ni = sN[i];

    float vals[TPK_SEG];
#pragma unroll
    for (int t = 0; t < TPK_SEG; t++) {
        int j = lane + (t << 5);
        float d = 0.f;
        d = fmaf(xi, sX[j], d); d = fmaf(yi, sY[j], d); d = fmaf(zi, sZ[j], d);
        vals[t] = 2.f * d - ni - sN[j];
    }

    float lmax = vals[0]; int lt = 0;
#pragma unroll
    for (int t = 1; t < TPK_SEG; t++)
        if (vals[t] > lmax) { lmax = vals[t]; lt = t; }

    int* orow = idxout + ((long)b * NPTS + i) * KNN;
    for (int r = 0; r < KNN; r++) {
        float v = lmax;
        int   j = lane + (lt << 5);
#pragma unroll
        for (int d = 16; d; d >>= 1) {
            float ov = __shfl_xor_sync(0xffffffffu, v, d);
            int   oj = __shfl_xor_sync(0xffffffffu, j, d);
            if (ov > v || (ov == v && oj < j)) { v = ov; j = oj; }
        }
        if (lane == 0) orow[r] = j;
        if ((j & 31) == lane) {
            vals[j >> 5] = -1e30f;
            lmax = vals[0]; lt = 0;
#pragma unroll
            for (int t = 1; t < TPK_SEG; t++)
                if (vals[t] > lmax) { lmax = vals[t]; lt = t; }
        }
    }
}

// ------------------------- layer-1 fused aggregate (K=3) ---------------------
__global__ void agg1_kernel(const float* __restrict__ X, const float* __restrict__ W1,
                            const int* __restrict__ idx,
                            const float* __restrict__ gv, const float* __restrict__ bv,
                            float* __restrict__ out, int ldout)
{
    int row = blockIdx.x;
    int b = row >> 11;
    int o = threadIdx.x;                 // 64
    __shared__ int   sidx[KNN];
    __shared__ float sxn[KNN][3];
    __shared__ float sxi[3];
    if (o < KNN) sidx[o] = idx[row * KNN + o];
    if (o < 3)   sxi[o]  = X[(long)row * 3 + o];
    __syncthreads();
    if (o < KNN) {
        long nr = (long)(b << 11) + sidx[o];
        sxn[o][0] = X[nr * 3]; sxn[o][1] = X[nr * 3 + 1]; sxn[o][2] = X[nr * 3 + 2];
    }
    __syncthreads();
    float wa0 = W1[o * 6],     wa1 = W1[o * 6 + 1], wa2 = W1[o * 6 + 2];
    float wd0 = W1[o * 6 + 3] - wa0, wd1 = W1[o * 6 + 4] - wa1, wd2 = W1[o * 6 + 5] - wa2;
    float ct = 0.f;
    ct = fmaf(wd0, sxi[0], ct); ct = fmaf(wd1, sxi[1], ct); ct = fmaf(wd2, sxi[2], ct);
    float gg = gv[o], bb = bv[o], m = -1e30f;
#pragma unroll
    for (int j = 0; j < KNN; j++) {
        float a = 0.f;
        a = fmaf(wa0, sxn[j][0], a); a = fmaf(wa1, sxn[j][1], a); a = fmaf(wa2, sxn[j][2], a);
        float v = a + ct;
        v = lrelu(gg * (v * BNS) + bb);
        m = fmaxf(m, v);
    }
    out[(long)row * ldout + o] = m;
}

// ------------------------- top-20 per row (layers 2-4) -----------------------
__global__ __launch_bounds__(256)
void topk_warp_kernel(const float* __restrict__ D, const float* __restrict__ xx,
                      int* __restrict__ idxout)
{
    int wid = threadIdx.x >> 5, lane = threadIdx.x & 31;
    int row = blockIdx.x * 8 + wid;
    int b = row >> 11, i = row & 2047;

    const float* Drow = D + (long)b * NPTS * NPTS + (long)i * NPTS;
    const float* xxb  = xx + b * NPTS;
    float xi = xxb[i];

    float vals[TPK_SEG];
#pragma unroll
    for (int t = 0; t < TPK_SEG; t++) {
        int j = lane + (t << 5);
        vals[t] = 2.f * Drow[j] - xi - xxb[j];
    }

    float lmax = vals[0]; int lt = 0;
#pragma unroll
    for (int t = 1; t < TPK_SEG; t++)
        if (vals[t] > lmax) { lmax = vals[t]; lt = t; }

    int* orow = idxout + row * KNN;
    for (int r = 0; r < KNN; r++) {
        float v = lmax;
        int   j = lane + (lt << 5);
#pragma unroll
        for (int d = 16; d; d >>= 1) {
            float ov = __shfl_xor_sync(0xffffffffu, v, d);
            int   oj = __shfl_xor_sync(0xffffffffu, j, d);
            if (ov > v || (ov == v && oj < j)) { v = ov; j = oj; }
        }
        if (lane == 0) orow[r] = j;
        if ((j & 31) == lane) {
            vals[j >> 5] = -1e30f;
            lmax = vals[0]; lt = 0;
#pragma unroll
            for (int t = 1; t < TPK_SEG; t++)
                if (vals[t] > lmax) { lmax = vals[t]; lt = t; }
        }
    }
}

// ------------------------- neighbor aggregate (merged A|Ct) ------------------
__global__ void agg_kernel(const float* __restrict__ ACt,
                           const int* __restrict__ idx,
                           const float* __restrict__ gv, const float* __restrict__ bv,
                           int O, float* __restrict__ out, int ldout)
{
    int row = blockIdx.x;
    int b = row >> 11;
    int o = threadIdx.x;
    int ld = 2 * O;
    __shared__ int sidx[KNN];
    if (o < KNN) sidx[o] = idx[row * KNN + o];
    __syncthreads();
    float c  = ACt[(long)row * ld + O + o];
    float gg = gv[o], bb = bv[o];
    float m = -1e30f;
#pragma unroll
    for (int j = 0; j < KNN; j++) {
        float v = ACt[((long)(b << 11) + sidx[j]) * ld + o] + c;
        v = lrelu(gg * (v * BNS) + bb);
        m = fmaxf(m, v);
    }
    out[(long)row * ldout + o] = m;
}

// ------------------------- pool combine --------------------------------------
__global__ void hcombine_kernel(const float* __restrict__ part, float* __restrict__ feat)
{
    int b = blockIdx.x, o = threadIdx.x;
    float mx = -1e30f, sm = 0.f;
    for (int c = 0; c < 16; c++) {
        mx = fmaxf(mx, part[(long)(b * 16 + c) * 2048 + o]);
        sm += part[(long)(b * 16 + c) * 2048 + 1024 + o];
    }
    feat[b * 2048 + o]        = mx;
    feat[b * 2048 + 1024 + o] = sm * (1.f / 2048.f);
}

// ------------------------- small FC -------------------------------------------
__global__ void fc_kernel(const float* __restrict__ in, int K,
                          const float* __restrict__ W, const float* __restrict__ bias,
                          const float* __restrict__ gv, const float* __restrict__ bv,
                          float* __restrict__ out, int O, int doLrelu)
{
    int gw = (blockIdx.x * blockDim.x + threadIdx.x) >> 5;
    int lane = threadIdx.x & 31;
    if (gw >= BATCH * O) return;
    int b = gw / O, o = gw % O;
    float s = 0.f;
    for (int k = lane; k < K; k += 32) s += in[b * K + k] * W[o * K + k];
#pragma unroll
    for (int d = 16; d; d >>= 1) s += __shfl_down_sync(0xffffffffu, s, d);
    if (lane == 0) {
        if (bias) s += bias[o];
        if (gv)   s = gv[o] * (s * BNS) + bv[o];
        if (doLrelu) s = lrelu(s);
        out[b * O + o] = s;
    }
}

// ============================================================================
static void edge_layer_tc(const float* Xin, int lda, int C,
                          const float* W, const float* gv, const float* bv, int O,
                          float* outcol, int ldout,
                          float* dD, float* dxx, int* didx, float* dACt,
                          __nv_bfloat16* dA3, __nv_bfloat16* dB3, __nv_bfloat16* dB3w)
{
    int K3 = 3 * C;
    int xt = (2 * O) / 128;            // 1 / 2 / 4 column tiles for [A|Ct]
    splitxx_kernel<<<NROWS * 32 / 256, 256>>>(Xin, lda, C, NROWS, dA3, dB3, dxx);
    wcatsplit_kernel<<<(2 * O * C + 255) / 256, 256>>>(W, C, O, dB3w);
    // one launch: lower-tri CTAs -> dist D (+ mirror), upper-tri CTAs -> [A|Ct]
    tc_gemm_kernel<true, false><<<dim3(NPTS / 128, NPTS / 128, BATCH), 256, SMEM_TC>>>(
        dA3, K3, (long)NPTS * K3, dB3, K3, (long)NPTS * K3,
        dD, NPTS, (long)NPTS * NPTS, K3, NPTS, nullptr, nullptr,
        dB3w, dACt, 2 * O, xt);
    topk_warp_kernel<<<NROWS / 8, 256>>>(dD, dxx, didx);
    agg_kernel<<<NROWS, O>>>(dACt, didx, gv, bv, O, outcol, ldout);
}

extern "C" void kernel_launch(void* const* d_in, const int* in_sizes, int n_in,
                              void* d_out, int out_size)
{
    const float* x   = (const float*)d_in[0];
    const float* W1  = (const float*)d_in[1];
    const float* g1  = (const float*)d_in[2];
    const float* b1  = (const float*)d_in[3];
    const float* W2  = (const float*)d_in[4];
    const float* g2  = (const float*)d_in[5];
    const float* b2  = (const float*)d_in[6];
    const float* W3  = (const float*)d_in[7];
    const float* g3  = (const float*)d_in[8];
    const float* b3  = (const float*)d_in[9];
    const float* W4  = (const float*)d_in[10];
    const float* g4  = (const float*)d_in[11];
    const float* b4  = (const float*)d_in[12];
    const float* W5  = (const float*)d_in[13];
    const float* g5  = (const float*)d_in[14];
    const float* b5  = (const float*)d_in[15];
    const float* L1  = (const float*)d_in[16];
    const float* g6  = (const float*)d_in[17];
    const float* b6  = (const float*)d_in[18];
    const float* L2  = (const float*)d_in[19];
    const float* L2b = (const float*)d_in[20];
    const float* g7  = (const float*)d_in[21];
    const float* b7  = (const float*)d_in[22];
    const float* L3  = (const float*)d_in[23];
    const float* L3b = (const float*)d_in[24];
    float* out = (float*)d_out;

    float *dD, *dxx, *dACt, *dXC, *dPart, *dFeat, *dFc1, *dFc2;
    int* didx;
    __nv_bfloat16 *dA3, *dB3, *dB3w;
    cudaGetSymbolAddress((void**)&dD,    g_D);
    cudaGetSymbolAddress((void**)&dxx,   g_xx);
    cudaGetSymbolAddress((void**)&didx,  g_idx);
    cudaGetSymbolAddress((void**)&dACt,  g_ACt);
    cudaGetSymbolAddress((void**)&dXC,   g_XC);
    cudaGetSymbolAddress((void**)&dPart, g_hpart);
    cudaGetSymbolAddress((void**)&dFeat, g_feat);
    cudaGetSymbolAddress((void**)&dFc1,  g_fc1);
    cudaGetSymbolAddress((void**)&dFc2,  g_fc2);
    cudaGetSymbolAddress((void**)&dA3,   g_A3);
    cudaGetSymbolAddress((void**)&dB3,   g_B3);
    cudaGetSymbolAddress((void**)&dB3w,  g_B3w);

    // raise dynamic smem limit for the pipelined GEMM (host-side, not captured)
    cudaFuncSetAttribute(tc_gemm_kernel<true, false>,
                         cudaFuncAttributeMaxDynamicSharedMemorySize, SMEM_TC);
    cudaFuncSetAttribute(tc_gemm_kernel<false, false>,
                         cudaFuncAttributeMaxDynamicSharedMemorySize, SMEM_TC);
    cudaFuncSetAttribute(tc_gemm_kernel<false, true>,
                         cudaFuncAttributeMaxDynamicSharedMemorySize, SMEM_TC);

    // ---- layer 1 (K=3): fused kNN + fused A/Ct aggregate ----
    knn3_fused_kernel<<<dim3(NPTS / 8, BATCH), 256>>>(x, didx);
    agg1_kernel<<<NROWS, 64>>>(x, W1, didx, g1, b1, dXC + 0, 512);

    // ---- layers 2-4: mma.sync path (dist + ACt in ONE launch) ----
    edge_layer_tc(dXC + 0,   512, 64,  W2, g2, b2,  64, dXC + 64,  512,
                  dD, dxx, didx, dACt, dA3, dB3, dB3w);
    edge_layer_tc(dXC + 64,  512, 64,  W3, g3, b3, 128, dXC + 128, 512,
                  dD, dxx, didx, dACt, dA3, dB3, dB3w);
    edge_layer_tc(dXC + 128, 512, 128, W4, g4, b4, 256, dXC + 256, 512,
                  dD, dxx, didx, dACt, dA3, dB3, dB3w);

    // ---- h = lrelu(bn(XC @ W5^T)) fused with global max/mean pooling ----
    {
        splitxx_kernel<<<NROWS * 32 / 256, 256>>>(dXC, 512, 512, NROWS, dA3, nullptr, nullptr);
        splitxx_kernel<<<1024 * 32 / 256, 256>>>(W5, 512, 512, 1024, nullptr, dB3w, nullptr);
        tc_gemm_kernel<false, true><<<dim3(1024 / 128, NROWS / 128, 1), 256, SMEM_TC>>>(
            dA3, 1536, 0, dB3w, 1536, 0, dPart, 0, 0, 1536, 1024, g5, b5,
            nullptr, nullptr, 0, 0);
    }

    // ---- pool combine + FC head ----
    hcombine_kernel<<<BATCH, 1024>>>(dPart, dFeat);
    fc_kernel<<<(BATCH * 512 * 32 + 255) / 256, 256>>>(dFeat, 2048, L1, nullptr, g6, b6, dFc1, 512, 1);
    fc_kernel<<<(BATCH * 256 * 32 + 255) / 256, 256>>>(dFc1,  512,  L2, L2b,    g7, b7, dFc2, 256, 1);
    fc_kernel<<<(BATCH * 10  * 32 + 255) / 256, 256>>>(dFc2,  256,  L3, L3b,    nullptr, nullptr, out, 10, 0);
}